// round 11
// baseline (speedup 1.0000x reference)
#include <cuda_runtime.h>
#include <cuda_bf16.h>
#include <math.h>

#define NN 50000
#define EE 800000
#define MT64 ((NN + 63) / 64)
#define NSZ (NN * 64)
#define NBLK_STATS 200
#define SCAN_B ((NN + 127) / 128)
#define TS 4352
typedef unsigned int u32;

// k_step smem (bytes): 4 bf16 A tiles (64r x 72 bf16 stride; hi 9216 + lo 9216 each)
#define AH 0
#define AHS 18432
#define AN 36864
#define AG 55296
#define BOFT 73728          // bf16 B: hi 9216 + lo 9216
#define BUFF 92160          // fp32 B: 64 x 68 floats
#define STEP_SMEM 109568

__device__ __forceinline__ u32 s2u(const void* p) {
    u32 a;
    asm("{ .reg .u64 t; cvta.to.shared.u64 t, %1; cvt.u32.u64 %0, t; }" : "=r"(a) : "l"(p));
    return a;
}
__device__ __forceinline__ void ldsm4(u32& r0, u32& r1, u32& r2, u32& r3, u32 a) {
    asm volatile("ldmatrix.sync.aligned.m8n8.x4.shared.b16 {%0,%1,%2,%3}, [%4];"
                 : "=r"(r0), "=r"(r1), "=r"(r2), "=r"(r3) : "r"(a));
}
__device__ __forceinline__ void ldsm2t(u32& r0, u32& r1, u32 a) {
    asm volatile("ldmatrix.sync.aligned.m8n8.x2.trans.shared.b16 {%0,%1}, [%2];"
                 : "=r"(r0), "=r"(r1) : "r"(a));
}
__device__ __forceinline__ void mma16816(float* c, u32 a0, u32 a1, u32 a2, u32 a3, u32 b0, u32 b1) {
    asm volatile("mma.sync.aligned.m16n8k16.row.col.f32.bf16.bf16.f32 "
                 "{%0,%1,%2,%3}, {%4,%5,%6,%7}, {%8,%9}, {%0,%1,%2,%3};"
                 : "+f"(c[0]), "+f"(c[1]), "+f"(c[2]), "+f"(c[3])
                 : "r"(a0), "r"(a1), "r"(a2), "r"(a3), "r"(b0), "r"(b1));
}
__device__ __forceinline__ void bsplit(float x, unsigned short& hb, unsigned short& lb) {
    __nv_bfloat16 h = __float2bfloat16_rn(x);
    float r = x - __bfloat162float(h);
    __nv_bfloat16 l = __float2bfloat16_rn(r);
    hb = *(unsigned short*)&h;
    lb = *(unsigned short*)&l;
}
__device__ __forceinline__ void store_split4(char* hp, char* lp, float4 v) {
    unsigned short h0, l0, h1, l1, h2, l2, h3, l3;
    bsplit(v.x, h0, l0); bsplit(v.y, h1, l1); bsplit(v.z, h2, l2); bsplit(v.w, h3, l3);
    *(uint2*)hp = make_uint2(((u32)h1 << 16) | h0, ((u32)h3 << 16) | h2);
    *(uint2*)lp = make_uint2(((u32)l1 << 16) | l0, ((u32)l3 << 16) | l2);
}

__device__ float g_stem[(size_t)NN * 192];
__device__ float g_x0[(size_t)NN * 64];
__device__ float g_a[(size_t)NN * 64];
__device__ float g_b[(size_t)NN * 64];
__device__ float g_cell0[(size_t)NN * 256];
__device__ float g_cell1[(size_t)NN * 256];
__device__ float g_sum[(size_t)5 * NSZ];
__device__ float g_nrm[(size_t)5 * NSZ];
__device__ __nv_bfloat16 g_wbkT[(size_t)28 * 4 * 8192];  // tensor: 4 relu panels, hi+lo [k][n]
__device__ float g_wbkF[(size_t)28 * 3 * 4096];           // ffma: 3 lin panels fp32 [k][n]
__device__ float g_wmix[14 * 8];
__device__ float g_stats[384];
__device__ float g_part[NBLK_STATS * 384];
__device__ float g_invdeg[NN];
__device__ float g_invsqrt[NN];
__device__ float g_ew[EE];
__device__ int g_deg[NN];
__device__ int g_cursor[NN];
__device__ int g_rowptr[NN + 1];
__device__ int g_eid[EE];
__device__ int g_srcs[EE];
__device__ int g_bsum[512];

// ---------------- CSR ----------------
__global__ void k_zero2(int* a, int* b) {
    int i = blockIdx.x * blockDim.x + threadIdx.x;
    if (i < NN) { a[i] = 0; b[i] = 0; }
}
__global__ void k_deg(const int* __restrict__ dst, int* __restrict__ deg) {
    int e = blockIdx.x * blockDim.x + threadIdx.x;
    if (e < EE) atomicAdd(&deg[dst[e]], 1);
}
__global__ void k_degfin(const int* __restrict__ deg, float* __restrict__ invdeg,
                         float* __restrict__ invsqrt) {
    int i = blockIdx.x * blockDim.x + threadIdx.x;
    if (i < NN) {
        float d = (float)max(deg[i], 1);
        invdeg[i] = 1.0f / d;
        invsqrt[i] = rsqrtf(d);
    }
}
__global__ void k_scan1(const int* __restrict__ deg, int* __restrict__ rowptr, int* __restrict__ bsum) {
    __shared__ int s[128];
    int b = blockIdx.x, t = threadIdx.x;
    int i = b * 128 + t;
    int v = (i < NN) ? deg[i] : 0;
    s[t] = v;
    __syncthreads();
    for (int off = 1; off < 128; off <<= 1) {
        int u = (t >= off) ? s[t - off] : 0;
        __syncthreads();
        s[t] += u;
        __syncthreads();
    }
    if (i < NN) rowptr[i] = s[t] - v;
    if (t == 127) bsum[b] = s[127];
}
__global__ void k_scan2(int* __restrict__ bsum) {
    __shared__ int s[512];
    int t = threadIdx.x;
    int v = (t < SCAN_B) ? bsum[t] : 0;
    s[t] = v;
    __syncthreads();
    for (int off = 1; off < 512; off <<= 1) {
        int u = (t >= off) ? s[t - off] : 0;
        __syncthreads();
        s[t] += u;
        __syncthreads();
    }
    if (t < SCAN_B) bsum[t] = s[t] - v;
}
__global__ void k_scan3(int* __restrict__ rowptr, const int* __restrict__ bsum) {
    int i = blockIdx.x * blockDim.x + threadIdx.x;
    if (i < NN) rowptr[i] += bsum[i >> 7];
    if (i == 0) rowptr[NN] = EE;
}
__global__ void k_scatter(const int* __restrict__ dst, const int* __restrict__ rowptr,
                          int* __restrict__ cursor, int* __restrict__ eid) {
    int e = blockIdx.x * blockDim.x + threadIdx.x;
    if (e < EE) {
        int d = dst[e];
        int pos = rowptr[d] + atomicAdd(&cursor[d], 1);
        eid[pos] = e;
    }
}
__global__ void k_sortfill(const int* __restrict__ rowptr, int* __restrict__ eid,
                           const int* __restrict__ src, const float* __restrict__ invsqrt,
                           int* __restrict__ srcs, float* __restrict__ ew) {
    int n = blockIdx.x * blockDim.x + threadIdx.x;
    if (n >= NN) return;
    int r0 = rowptr[n], r1 = rowptr[n + 1];
    for (int i = r0 + 1; i < r1; i++) {
        int key = eid[i];
        int j = i - 1;
        while (j >= r0 && eid[j] > key) { eid[j + 1] = eid[j]; j--; }
        eid[j + 1] = key;
    }
    float isd = invsqrt[n];
    for (int p = r0; p < r1; p++) {
        int e = eid[p];
        int s = src[e];
        srcs[p] = s;
        ew[p] = invsqrt[s] * isd;
    }
}
__global__ void k_softmax(const float* __restrict__ alphas, float* __restrict__ wmix) {
    int r = threadIdx.x;
    if (r >= 14) return;
    float m = -1e30f;
    for (int o = 0; o < 8; o++) m = fmaxf(m, alphas[r * 8 + o]);
    float e[8], s = 0.f;
    for (int o = 0; o < 8; o++) { e[o] = expf(alphas[r * 8 + o] - m); s += e[o]; }
    float inv = 1.0f / s;
    for (int o = 0; o < 8; o++) wmix[r * 8 + o] = e[o] * inv;
}

// Tensor relu panels (bf16 split): 0 gcn(norm), 1 gin(hs), 2 mlp(h), 3 gcnii(gmix)
// FFMA lin panels (fp32): 0 h@(w3Wss+w5(Wgc1-Wgc2)+w1 I), 1 s@w3Wsn (x invdeg), 2 hs@w5Wgc2
__global__ void k_bake(const float* __restrict__ wmix,
                       const float* __restrict__ Wgcn, const float* __restrict__ Wss,
                       const float* __restrict__ Wsn, const float* __restrict__ Wgin,
                       const float* __restrict__ Wgc1, const float* __restrict__ Wgc2,
                       const float* __restrict__ Wmlp, const float* __restrict__ Wgcnii,
                       __nv_bfloat16* __restrict__ wbT, float* __restrict__ wbF) {
    int s = blockIdx.x;
    int ej = s % 14;
    const float* wv = wmix + ej * 8;
    size_t o = (size_t)s * 4096;
    __nv_bfloat16* obT = wbT + (size_t)s * 4 * 8192;
    float* obF = wbF + (size_t)s * 3 * 4096;
    float w1 = wv[1], w2 = wv[2], w3 = wv[3], w4 = wv[4], w5 = wv[5], w6 = wv[6], w7 = wv[7];
    for (int idx = threadIdx.x; idx < 4096; idx += blockDim.x) {
        int k = idx >> 6, n = idx & 63;
        float tv[4];
        tv[0] = w2 * Wgcn[o + idx];
        tv[1] = w4 * Wgin[o + idx];
        tv[2] = w6 * Wmlp[o + idx];
        tv[3] = w7 * Wgcnii[o + idx];
        for (int p = 0; p < 4; p++) {
            unsigned short hb, lb;
            bsplit(tv[p], hb, lb);
            obT[p * 8192 + idx] = *(__nv_bfloat16*)&hb;
            obT[p * 8192 + 4096 + idx] = *(__nv_bfloat16*)&lb;
        }
        obF[0 * 4096 + idx] = w3 * Wss[o + idx] + w5 * (Wgc1[o + idx] - Wgc2[o + idx]) + ((k == n) ? w1 : 0.f);
        obF[1 * 4096 + idx] = w3 * Wsn[o + idx];
        obF[2 * 4096 + idx] = w5 * Wgc2[o + idx];
    }
}

// ---------------- fp32 tiled GEMM (stem/pre) ----------------
__global__ __launch_bounds__(256) void k_gemm(const float* __restrict__ A, int lda,
                                              const float* __restrict__ B, int ldb,
                                              float* __restrict__ C, int K) {
    __shared__ float As[TS];
    __shared__ float Bs[TS];
    const int tid = threadIdx.x;
    const int m0 = blockIdx.x * 64;
    const int n0b = blockIdx.y * 64;
    const int n0 = (tid & 15) * 4, mm0 = (tid >> 4) * 4;
    float acc[16];
#pragma unroll
    for (int i = 0; i < 16; i++) acc[i] = 0.f;
    for (int kt = 0; kt < K; kt += 64) {
        __syncthreads();
#pragma unroll
        for (int i = 0; i < 16; i++) {
            int idx = tid + i * 256;
            int m = idx >> 6, k = idx & 63;
            int gm = m0 + m;
            As[k * 68 + m] = (gm < NN) ? A[(size_t)gm * lda + kt + k] : 0.f;
            Bs[(idx >> 6) * 68 + (idx & 63)] = B[(size_t)(kt + (idx >> 6)) * ldb + n0b + (idx & 63)];
        }
        __syncthreads();
#pragma unroll 16
        for (int k = 0; k < 64; k++) {
            float4 a4 = *(const float4*)&As[k * 68 + mm0];
            float4 b4 = *(const float4*)&Bs[k * 68 + n0];
            acc[0] += a4.x * b4.x; acc[1] += a4.x * b4.y; acc[2] += a4.x * b4.z; acc[3] += a4.x * b4.w;
            acc[4] += a4.y * b4.x; acc[5] += a4.y * b4.y; acc[6] += a4.y * b4.z; acc[7] += a4.y * b4.w;
            acc[8] += a4.z * b4.x; acc[9] += a4.z * b4.y; acc[10] += a4.z * b4.z; acc[11] += a4.z * b4.w;
            acc[12] += a4.w * b4.x; acc[13] += a4.w * b4.y; acc[14] += a4.w * b4.z; acc[15] += a4.w * b4.w;
        }
    }
#pragma unroll
    for (int r = 0; r < 4; r++) {
        int gm = m0 + mm0 + r;
        if (gm < NN)
            *(float4*)&C[(size_t)gm * ldb + n0b + n0] =
                make_float4(acc[r * 4], acc[r * 4 + 1], acc[r * 4 + 2], acc[r * 4 + 3]);
    }
}

// ---------------- batchnorm + agg ----------------
__global__ void k_colstats(const float* __restrict__ A, int ncols, float* __restrict__ part) {
    int blk = blockIdx.x, c = threadIdx.x;
    int rows_per = (NN + NBLK_STATS - 1) / NBLK_STATS;
    int r0 = blk * rows_per, r1 = min(NN, r0 + rows_per);
    float s = 0.f, s2 = 0.f;
    if (c < ncols)
        for (int r = r0; r < r1; r++) {
            float v = A[(size_t)r * ncols + c];
            s += v; s2 += v * v;
        }
    part[blk * 384 + c] = s;
    part[blk * 384 + 192 + c] = s2;
}
__global__ void k_colfin(const float* __restrict__ part, int ncols, float* __restrict__ stats) {
    int c = threadIdx.x;
    if (c >= ncols) return;
    float s = 0.f, s2 = 0.f;
    for (int b = 0; b < NBLK_STATS; b++) { s += part[b * 384 + c]; s2 += part[b * 384 + 192 + c]; }
    float m = s / (float)NN;
    float v = s2 / (float)NN - m * m;
    stats[c] = m;
    stats[192 + c] = rsqrtf(v + 1e-5f);
}
__global__ void k_bnapply(float* __restrict__ A, int ncols, const float* __restrict__ stats, int dorelu) {
    size_t idx = (size_t)blockIdx.x * blockDim.x + threadIdx.x;
    if (idx >= (size_t)NN * ncols) return;
    int c = (int)(idx % ncols);
    float v = (A[idx] - stats[c]) * stats[192 + c];
    if (dorelu) v = fmaxf(v, 0.f);
    A[idx] = v;
}
__global__ void k_agg(const float* __restrict__ h, int ldh, const int* __restrict__ rowptr,
                      const int* __restrict__ srcs, const float* __restrict__ ew,
                      float* __restrict__ osum, float* __restrict__ onrm) {
    int warp = (blockIdx.x * blockDim.x + threadIdx.x) >> 5;
    if (warp >= NN) return;
    int lane = threadIdx.x & 31;
    int r0 = rowptr[warp], r1 = rowptr[warp + 1];
    float2 s = make_float2(0.f, 0.f), nrm = make_float2(0.f, 0.f);
    for (int p = r0; p < r1; p++) {
        int si = srcs[p];
        float w = ew[p];
        float2 v = *(const float2*)&h[(size_t)si * ldh + lane * 2];
        s.x += v.x; s.y += v.y;
        nrm.x += w * v.x; nrm.y += w * v.y;
    }
    *(float2*)&osum[(size_t)warp * 64 + lane * 2] = s;
    *(float2*)&onrm[(size_t)warp * 64 + lane * 2] = nrm;
}

// ---------------- dual-pipe step kernel: tensor(4 relu) + FFMA(3 lin) ----------------
__global__ __launch_bounds__(128, 2) void k_step(
    const float* __restrict__ h0p, const float* __restrict__ h1p, const float* __restrict__ h2p,
    const float* __restrict__ h3p, const float* __restrict__ h4p,
    int l0, int l1, int l2, int l3, int l4,
    const float* __restrict__ sums, const float* __restrict__ nrms,
    const float* __restrict__ x0, const float* __restrict__ invdeg,
    const __nv_bfloat16* __restrict__ wbT, const float* __restrict__ wbF,
    int nst, float* __restrict__ outp) {
    extern __shared__ char smc[];
    const u32 sb = s2u(smc);
    const int tid = threadIdx.x, wid = tid >> 5, lane = tid & 31;
    const int m0 = blockIdx.x * 64;
    const int wrow = wid * 16;
    const int frow = tid >> 1, fcb = (tid & 1) * 32;   // FFMA row-layout ownership
    const bool frv = (m0 + frow) < NN;
    const float idgR = frv ? invdeg[m0 + frow] : 0.f;
    const int fg = lane >> 2, tig = lane & 3;          // fragment ownership

    float outf[32], outr[32];
#pragma unroll
    for (int i = 0; i < 32; i++) { outf[i] = 0.f; outr[i] = 0.f; }
    uint4 pfT[8], pfF[8];
    {
        const uint4* s = (const uint4*)wbT;
#pragma unroll
        for (int i = 0; i < 8; i++) pfT[i] = s[tid + i * 128];
    }
    {
        const uint4* s = (const uint4*)wbF;
#pragma unroll
        for (int i = 0; i < 8; i++) pfF[i] = s[tid + i * 128];
    }
    int tnext = 1, fnext = 1;

    for (int j = 0; j < nst; j++) {
        const float* h = (j == 0) ? h0p : (j == 1) ? h1p : (j == 2) ? h2p : (j == 3) ? h3p : h4p;
        int ldh = (j == 0) ? l0 : (j == 1) ? l1 : (j == 2) ? l2 : (j == 3) ? l3 : l4;
        const float* ssum = sums + (size_t)j * NSZ;
        const float* snrm = nrms + (size_t)j * NSZ;

        __syncthreads();  // prev slot fully done reading A tiles
#pragma unroll
        for (int i = 0; i < 8; i++) {
            int idx = tid + i * 128;
            int row = idx >> 4, cg = (idx & 15) * 4;
            int gm = m0 + row;
            float4 z = make_float4(0.f, 0.f, 0.f, 0.f);
            float4 hv = z, sv = z, nv = z, xv = z;
            if (gm < NN) {
                hv = *(const float4*)(h + (size_t)gm * ldh + cg);
                sv = *(const float4*)(ssum + (size_t)gm * 64 + cg);
                nv = *(const float4*)(snrm + (size_t)gm * 64 + cg);
                xv = *(const float4*)(x0 + (size_t)gm * 64 + cg);
            }
            float4 hs = make_float4(hv.x + sv.x, hv.y + sv.y, hv.z + sv.z, hv.w + sv.w);
            float4 gv = make_float4(0.9f * nv.x + 0.1f * xv.x, 0.9f * nv.y + 0.1f * xv.y,
                                    0.9f * nv.z + 0.1f * xv.z, 0.9f * nv.w + 0.1f * xv.w);
            int off = row * 144 + cg * 2;
            store_split4(smc + AH + off, smc + AH + 9216 + off, hv);
            store_split4(smc + AHS + off, smc + AHS + 9216 + off, hs);
            store_split4(smc + AN + off, smc + AN + 9216 + off, nv);
            store_split4(smc + AG + off, smc + AG + 9216 + off, gv);
        }
        const float* hrow = h + (size_t)(m0 + frow) * ldh;
        const float* srow = ssum + (size_t)(m0 + frow) * 64;

#pragma unroll 1
        for (int r = 0; r < 4; r++) {
            __syncthreads();  // A ready (r==0) / B buffers free
#pragma unroll
            for (int i = 0; i < 8; i++) {   // publish bf16 tensor panel
                int u = tid + i * 128;
                int rr = u >> 3, c = u & 7;
                int dst = BOFT + ((rr < 64) ? (rr * 144 + c * 16) : (9216 + (rr - 64) * 144 + c * 16));
                *(uint4*)(smc + dst) = pfT[i];
            }
            if (r < 3) {
#pragma unroll
                for (int i = 0; i < 8; i++) {  // publish fp32 lin panel (stride 68)
                    int u = tid + i * 128;
                    int rr = u >> 4, c4 = (u & 15) * 4;
                    *(uint4*)(smc + BUFF + (rr * 68 + c4) * 4) = pfF[i];
                }
            }
            __syncthreads();
            if (tnext < nst * 4) {
                const uint4* s = (const uint4*)(wbT + (size_t)tnext * 8192);
#pragma unroll
                for (int i = 0; i < 8; i++) pfT[i] = s[tid + i * 128];
            }
            tnext++;
            if (r < 3) {
                if (fnext < nst * 3) {
                    const uint4* s = (const uint4*)(wbF + (size_t)fnext * 4096);
#pragma unroll
                    for (int i = 0; i < 8; i++) pfF[i] = s[tid + i * 128];
                }
                fnext++;
            }
            float tc[32];
#pragma unroll
            for (int i = 0; i < 32; i++) tc[i] = 0.f;
            const u32 At = sb + ((r == 0) ? AN : (r == 1) ? AHS : (r == 2) ? AH : AG);
#pragma unroll
            for (int q = 0; q < 4; q++) {
                // ---- tensor kc=q ----
                u32 aAddr = At + (u32)((wrow + (lane & 7) + ((lane >> 3) & 1) * 8) * 144 + q * 32 + (lane >> 4) * 16);
                u32 a0, a1, a2, a3, e0, e1, e2, e3;
                ldsm4(a0, a1, a2, a3, aAddr);
                ldsm4(e0, e1, e2, e3, aAddr + 9216);
                u32 bRow = sb + BOFT + (u32)((q * 16 + (lane & 15)) * 144);
#pragma unroll
                for (int nb = 0; nb < 8; nb++) {
                    u32 b0, b1, c0, c1;
                    ldsm2t(b0, b1, bRow + nb * 16);
                    ldsm2t(c0, c1, bRow + nb * 16 + 9216);
                    mma16816(tc + nb * 4, a0, a1, a2, a3, b0, b1);
                    mma16816(tc + nb * 4, e0, e1, e2, e3, b0, b1);
                    mma16816(tc + nb * 4, a0, a1, a2, a3, c0, c1);
                }
                // ---- FFMA quarter (16 k) ----
                if (r < 3) {
                    const float* bbase = (const float*)(smc + BUFF) + fcb;
#pragma unroll
                    for (int k4 = 0; k4 < 4; k4++) {
                        int k0 = q * 16 + k4 * 4;
                        float4 av = make_float4(0.f, 0.f, 0.f, 0.f);
                        if (frv) {
                            if (r == 0) av = *(const float4*)(hrow + k0);
                            else if (r == 1) {
                                av = *(const float4*)(srow + k0);
                                av.x *= idgR; av.y *= idgR; av.z *= idgR; av.w *= idgR;
                            } else {
                                float4 u = *(const float4*)(hrow + k0);
                                float4 v = *(const float4*)(srow + k0);
                                av = make_float4(u.x + v.x, u.y + v.y, u.z + v.z, u.w + v.w);
                            }
                        }
#pragma unroll
                        for (int kk = 0; kk < 4; kk++) {
                            float a = (kk == 0) ? av.x : (kk == 1) ? av.y : (kk == 2) ? av.z : av.w;
                            const float* br = bbase + (k0 + kk) * 68;
#pragma unroll
                            for (int i2 = 0; i2 < 8; i2++) {
                                float4 b = *(const float4*)(br + i2 * 4);
                                outr[i2 * 4 + 0] += a * b.x;
                                outr[i2 * 4 + 1] += a * b.y;
                                outr[i2 * 4 + 2] += a * b.z;
                                outr[i2 * 4 + 3] += a * b.w;
                            }
                        }
                    }
                }
            }
#pragma unroll
            for (int i = 0; i < 32; i++) outf[i] += fmaxf(tc[i], 0.f);
        }
    }
    // combine: FFMA partials first, then tensor fragment RMW
    if (frv) {
        float* orow = outp + (size_t)(m0 + frow) * 256 + fcb;
#pragma unroll
        for (int i = 0; i < 8; i++)
            *(float4*)(orow + i * 4) =
                make_float4(outr[i * 4], outr[i * 4 + 1], outr[i * 4 + 2], outr[i * 4 + 3]);
    }
    __syncthreads();
    int r0g = m0 + wrow + fg, r1g = r0g + 8;
#pragma unroll
    for (int nb = 0; nb < 8; nb++) {
        int c = nb * 8 + tig * 2;
        if (r0g < NN) {
            float* p = outp + (size_t)r0g * 256 + c;
            p[0] += outf[nb * 4 + 0];
            p[1] += outf[nb * 4 + 1];
        }
        if (r1g < NN) {
            float* p = outp + (size_t)r1g * 256 + c;
            p[0] += outf[nb * 4 + 2];
            p[1] += outf[nb * 4 + 3];
        }
    }
}

__global__ void k_cls(const float* __restrict__ s1, const float* __restrict__ W,
                      const float* __restrict__ b, float* __restrict__ out) {
    int n = blockIdx.x;
    __shared__ float row[256];
    __shared__ float red[64];
    int tid = threadIdx.x;
    float ls = 0.f;
#pragma unroll
    for (int i = 0; i < 4; i++) {
        float v = s1[(size_t)n * 256 + tid + i * 64];
        row[tid + i * 64] = v;
        ls += v;
    }
    red[tid] = ls;
    __syncthreads();
    for (int off = 32; off > 0; off >>= 1) {
        if (tid < off) red[tid] += red[tid + off];
        __syncthreads();
    }
    float pooled = red[0] * (1.0f / 256.0f);
    if (tid < 40) {
        float acc = b[tid] + pooled * W[tid];
#pragma unroll 8
        for (int k = 0; k < 256; k++) acc += row[k] * W[(1 + k) * 40 + tid];
        out[(size_t)n * 40 + tid] = acc;
    }
}

static void bnrun(float* buf, int ncols, int dorelu, float* part, float* stats) {
    k_colstats<<<NBLK_STATS, 192>>>(buf, ncols, part);
    k_colfin<<<1, 192>>>(part, ncols, stats);
    size_t total = (size_t)NN * ncols;
    k_bnapply<<<(int)((total + 255) / 256), 256>>>(buf, ncols, stats, dorelu);
}

extern "C" void kernel_launch(void* const* d_in, const int* in_sizes, int n_in,
                              void* d_out, int out_size) {
    const float* x = (const float*)d_in[0];
    const int* ei = (const int*)d_in[1];
    const float* alphas = (const float*)d_in[2];
    const float* stemW = (const float*)d_in[3];
    const float* preW = (const float*)d_in[4];
    const float* p0W0 = (const float*)d_in[5];
    const float* p1W0 = (const float*)d_in[6];
    const float* p0W1 = (const float*)d_in[7];
    const float* p1W1 = (const float*)d_in[8];
    const float* Wgcn = (const float*)d_in[9];
    const float* Wss = (const float*)d_in[10];
    const float* Wsn = (const float*)d_in[11];
    const float* Wgin = (const float*)d_in[12];
    const float* Wgc1 = (const float*)d_in[13];
    const float* Wgc2 = (const float*)d_in[14];
    const float* Wmlp = (const float*)d_in[15];
    const float* Wgcnii = (const float*)d_in[16];
    const float* clsW = (const float*)d_in[17];
    const float* clsb = (const float*)d_in[18];
    float* out = (float*)d_out;
    const int* srcI = ei;
    const int* dstI = ei + EE;

    float *stem, *x0p, *ap, *bp, *c0, *c1, *sums, *nrms, *wmix, *stats, *part;
    float *invdeg, *invsqrt, *ew, *wbF;
    __nv_bfloat16* wbT;
    int *deg, *cursor, *rowptr, *eid, *srcs, *bsum;
    cudaGetSymbolAddress((void**)&stem, g_stem);
    cudaGetSymbolAddress((void**)&x0p, g_x0);
    cudaGetSymbolAddress((void**)&ap, g_a);
    cudaGetSymbolAddress((void**)&bp, g_b);
    cudaGetSymbolAddress((void**)&c0, g_cell0);
    cudaGetSymbolAddress((void**)&c1, g_cell1);
    cudaGetSymbolAddress((void**)&sums, g_sum);
    cudaGetSymbolAddress((void**)&nrms, g_nrm);
    cudaGetSymbolAddress((void**)&wbT, g_wbkT);
    cudaGetSymbolAddress((void**)&wbF, g_wbkF);
    cudaGetSymbolAddress((void**)&wmix, g_wmix);
    cudaGetSymbolAddress((void**)&stats, g_stats);
    cudaGetSymbolAddress((void**)&part, g_part);
    cudaGetSymbolAddress((void**)&invdeg, g_invdeg);
    cudaGetSymbolAddress((void**)&invsqrt, g_invsqrt);
    cudaGetSymbolAddress((void**)&ew, g_ew);
    cudaGetSymbolAddress((void**)&deg, g_deg);
    cudaGetSymbolAddress((void**)&cursor, g_cursor);
    cudaGetSymbolAddress((void**)&rowptr, g_rowptr);
    cudaGetSymbolAddress((void**)&eid, g_eid);
    cudaGetSymbolAddress((void**)&srcs, g_srcs);
    cudaGetSymbolAddress((void**)&bsum, g_bsum);

    cudaFuncSetAttribute(k_step, cudaFuncAttributeMaxDynamicSharedMemorySize, STEP_SMEM);

    k_zero2<<<(NN + 255) / 256, 256>>>(deg, cursor);
    k_deg<<<(EE + 255) / 256, 256>>>(dstI, deg);
    k_degfin<<<(NN + 255) / 256, 256>>>(deg, invdeg, invsqrt);
    k_scan1<<<SCAN_B, 128>>>(deg, rowptr, bsum);
    k_scan2<<<1, 512>>>(bsum);
    k_scan3<<<(NN + 255) / 256, 256>>>(rowptr, bsum);
    k_scatter<<<(EE + 255) / 256, 256>>>(dstI, rowptr, cursor, eid);
    k_sortfill<<<(NN + 127) / 128, 128>>>(rowptr, eid, srcI, invsqrt, srcs, ew);

    k_softmax<<<1, 16>>>(alphas, wmix);
    k_bake<<<28, 256>>>(wmix, Wgcn, Wss, Wsn, Wgin, Wgc1, Wgc2, Wmlp, Wgcnii, wbT, wbF);

    k_gemm<<<dim3(MT64, 3), 256>>>(x, 128, stemW, 192, stem, 128);
    bnrun(stem, 192, 0, part, stats);
    k_gemm<<<dim3(MT64, 1), 256>>>(x, 128, preW, 64, x0p, 128);
    bnrun(x0p, 64, 1, part, stats);

    const int aggBlocks = (NN * 32 + 255) / 256;
    for (int ci = 0; ci < 2; ci++) {
        const float* s0 = stem; int k0 = 192;
        const float* s1 = (ci == 0) ? stem : c0;
        int k1 = (ci == 0) ? 192 : 256;
        const float* pW0 = (ci == 0) ? p0W0 : p0W1;
        const float* pW1 = (ci == 0) ? p1W0 : p1W1;
        float* cell = (ci == 0) ? c0 : c1;

        k_gemm<<<dim3(MT64, 1), 256>>>(s0, k0, pW0, 64, ap, k0);
        bnrun(ap, 64, 1, part, stats);
        k_gemm<<<dim3(MT64, 1), 256>>>(s1, k1, pW1, 64, bp, k1);
        bnrun(bp, 64, 1, part, stats);

        const float* sp[5] = {ap, bp, cell, cell + 64, cell + 128};
        const int sl[5] = {64, 64, 256, 256, 256};
        k_agg<<<aggBlocks, 256>>>(sp[0], sl[0], rowptr, srcs, ew, sums, nrms);
        k_agg<<<aggBlocks, 256>>>(sp[1], sl[1], rowptr, srcs, ew, sums + (size_t)NSZ, nrms + (size_t)NSZ);

        int ej0 = 0;
        for (int t = 0; t < 4; t++) {
            int slot0 = ci * 14 + ej0;
            k_step<<<MT64, 128, STEP_SMEM>>>(sp[0], sp[1], sp[2], sp[3], sp[4],
                                             sl[0], sl[1], sl[2], sl[3], sl[4],
                                             sums, nrms, x0p, invdeg,
                                             wbT + (size_t)slot0 * 4 * 8192,
                                             wbF + (size_t)slot0 * 3 * 4096,
                                             t + 2, cell + t * 64);
            ej0 += t + 2;
            if (t < 3) {
                int ns = t + 2;
                k_agg<<<aggBlocks, 256>>>(sp[ns], sl[ns], rowptr, srcs, ew,
                                          sums + (size_t)ns * NSZ, nrms + (size_t)ns * NSZ);
            }
        }
    }
    k_cls<<<NN, 64>>>(c1, clsW, clsb, out);
}

// round 12
// speedup vs baseline: 1.1818x; 1.1818x over previous
#include <cuda_runtime.h>
#include <cuda_bf16.h>
#include <math.h>

#define NN 50000
#define EE 800000
#define MT64 ((NN + 63) / 64)
#define NSZ (NN * 64)
#define NBLK_STATS 200
#define SCAN_B ((NN + 127) / 128)
#define TS 4352
typedef unsigned int u32;

// k_step smem: 4 bf16 A tiles (64r x 72 stride; hi 9216 + lo 9216), bf16 B, fp32 B
#define AH 0
#define AHS 18432
#define AN 36864
#define AG 55296
#define BOFT 73728          // bf16 B: hi 9216 + lo 9216
#define BF 92160            // fp32 B: 64x64 = 16384
#define STEP_SMEM 108544

__device__ __forceinline__ u32 s2u(const void* p) {
    u32 a;
    asm("{ .reg .u64 t; cvta.to.shared.u64 t, %1; cvt.u32.u64 %0, t; }" : "=r"(a) : "l"(p));
    return a;
}
__device__ __forceinline__ void ldsm4(u32& r0, u32& r1, u32& r2, u32& r3, u32 a) {
    asm volatile("ldmatrix.sync.aligned.m8n8.x4.shared.b16 {%0,%1,%2,%3}, [%4];"
                 : "=r"(r0), "=r"(r1), "=r"(r2), "=r"(r3) : "r"(a));
}
__device__ __forceinline__ void ldsm2t(u32& r0, u32& r1, u32 a) {
    asm volatile("ldmatrix.sync.aligned.m8n8.x2.trans.shared.b16 {%0,%1}, [%2];"
                 : "=r"(r0), "=r"(r1) : "r"(a));
}
__device__ __forceinline__ void mma16816(float* c, u32 a0, u32 a1, u32 a2, u32 a3, u32 b0, u32 b1) {
    asm volatile("mma.sync.aligned.m16n8k16.row.col.f32.bf16.bf16.f32 "
                 "{%0,%1,%2,%3}, {%4,%5,%6,%7}, {%8,%9}, {%0,%1,%2,%3};"
                 : "+f"(c[0]), "+f"(c[1]), "+f"(c[2]), "+f"(c[3])
                 : "r"(a0), "r"(a1), "r"(a2), "r"(a3), "r"(b0), "r"(b1));
}
#define BAR_T() asm volatile("bar.sync 1, 128;" ::: "memory")
#define BAR_F() asm volatile("bar.sync 2, 64;" ::: "memory")

__device__ __forceinline__ void bsplit(float x, unsigned short& hb, unsigned short& lb) {
    __nv_bfloat16 h = __float2bfloat16_rn(x);
    float r = x - __bfloat162float(h);
    __nv_bfloat16 l = __float2bfloat16_rn(r);
    hb = *(unsigned short*)&h;
    lb = *(unsigned short*)&l;
}
__device__ __forceinline__ void store_split4(char* hp, char* lp, float4 v) {
    unsigned short h0, l0, h1, l1, h2, l2, h3, l3;
    bsplit(v.x, h0, l0); bsplit(v.y, h1, l1); bsplit(v.z, h2, l2); bsplit(v.w, h3, l3);
    *(uint2*)hp = make_uint2(((u32)h1 << 16) | h0, ((u32)h3 << 16) | h2);
    *(uint2*)lp = make_uint2(((u32)l1 << 16) | l0, ((u32)l3 << 16) | l2);
}

__device__ float g_stem[(size_t)NN * 192];
__device__ float g_x0[(size_t)NN * 64];
__device__ float g_a[(size_t)NN * 64];
__device__ float g_b[(size_t)NN * 64];
__device__ float g_cell0[(size_t)NN * 256];
__device__ float g_cell1[(size_t)NN * 256];
__device__ float g_sum[(size_t)5 * NSZ];
__device__ float g_nrm[(size_t)5 * NSZ];
__device__ __nv_bfloat16 g_wbkT[(size_t)28 * 4 * 8192];  // tensor: 4 relu panels, hi+lo [k][n]
__device__ float g_wbkF[(size_t)28 * 3 * 4096];           // ffma: 3 lin panels fp32 [k][n]
__device__ float g_wmix[14 * 8];
__device__ float g_stats[384];
__device__ float g_part[NBLK_STATS * 384];
__device__ float g_invdeg[NN];
__device__ float g_invsqrt[NN];
__device__ float g_ew[EE];
__device__ int g_deg[NN];
__device__ int g_cursor[NN];
__device__ int g_rowptr[NN + 1];
__device__ int g_eid[EE];
__device__ int g_srcs[EE];
__device__ int g_bsum[512];

// ---------------- CSR ----------------
__global__ void k_zero2(int* a, int* b) {
    int i = blockIdx.x * blockDim.x + threadIdx.x;
    if (i < NN) { a[i] = 0; b[i] = 0; }
}
__global__ void k_deg(const int* __restrict__ dst, int* __restrict__ deg) {
    int e = blockIdx.x * blockDim.x + threadIdx.x;
    if (e < EE) atomicAdd(&deg[dst[e]], 1);
}
__global__ void k_degfin(const int* __restrict__ deg, float* __restrict__ invdeg,
                         float* __restrict__ invsqrt) {
    int i = blockIdx.x * blockDim.x + threadIdx.x;
    if (i < NN) {
        float d = (float)max(deg[i], 1);
        invdeg[i] = 1.0f / d;
        invsqrt[i] = rsqrtf(d);
    }
}
__global__ void k_scan1(const int* __restrict__ deg, int* __restrict__ rowptr, int* __restrict__ bsum) {
    __shared__ int s[128];
    int b = blockIdx.x, t = threadIdx.x;
    int i = b * 128 + t;
    int v = (i < NN) ? deg[i] : 0;
    s[t] = v;
    __syncthreads();
    for (int off = 1; off < 128; off <<= 1) {
        int u = (t >= off) ? s[t - off] : 0;
        __syncthreads();
        s[t] += u;
        __syncthreads();
    }
    if (i < NN) rowptr[i] = s[t] - v;
    if (t == 127) bsum[b] = s[127];
}
__global__ void k_scan2(int* __restrict__ bsum) {
    __shared__ int s[512];
    int t = threadIdx.x;
    int v = (t < SCAN_B) ? bsum[t] : 0;
    s[t] = v;
    __syncthreads();
    for (int off = 1; off < 512; off <<= 1) {
        int u = (t >= off) ? s[t - off] : 0;
        __syncthreads();
        s[t] += u;
        __syncthreads();
    }
    if (t < SCAN_B) bsum[t] = s[t] - v;
}
__global__ void k_scan3(int* __restrict__ rowptr, const int* __restrict__ bsum) {
    int i = blockIdx.x * blockDim.x + threadIdx.x;
    if (i < NN) rowptr[i] += bsum[i >> 7];
    if (i == 0) rowptr[NN] = EE;
}
__global__ void k_scatter(const int* __restrict__ dst, const int* __restrict__ rowptr,
                          int* __restrict__ cursor, int* __restrict__ eid) {
    int e = blockIdx.x * blockDim.x + threadIdx.x;
    if (e < EE) {
        int d = dst[e];
        int pos = rowptr[d] + atomicAdd(&cursor[d], 1);
        eid[pos] = e;
    }
}
__global__ void k_sortfill(const int* __restrict__ rowptr, int* __restrict__ eid,
                           const int* __restrict__ src, const float* __restrict__ invsqrt,
                           int* __restrict__ srcs, float* __restrict__ ew) {
    int n = blockIdx.x * blockDim.x + threadIdx.x;
    if (n >= NN) return;
    int r0 = rowptr[n], r1 = rowptr[n + 1];
    for (int i = r0 + 1; i < r1; i++) {
        int key = eid[i];
        int j = i - 1;
        while (j >= r0 && eid[j] > key) { eid[j + 1] = eid[j]; j--; }
        eid[j + 1] = key;
    }
    float isd = invsqrt[n];
    for (int p = r0; p < r1; p++) {
        int e = eid[p];
        int s = src[e];
        srcs[p] = s;
        ew[p] = invsqrt[s] * isd;
    }
}
__global__ void k_softmax(const float* __restrict__ alphas, float* __restrict__ wmix) {
    int r = threadIdx.x;
    if (r >= 14) return;
    float m = -1e30f;
    for (int o = 0; o < 8; o++) m = fmaxf(m, alphas[r * 8 + o]);
    float e[8], s = 0.f;
    for (int o = 0; o < 8; o++) { e[o] = expf(alphas[r * 8 + o] - m); s += e[o]; }
    float inv = 1.0f / s;
    for (int o = 0; o < 8; o++) wmix[r * 8 + o] = e[o] * inv;
}

// Tensor relu panels (bf16 split): 0 gcn(norm), 1 gin(hs), 2 mlp(h), 3 gcnii(gmix)
// FFMA lin panels (fp32): 0 h@(w3Wss+w5(Wgc1-Wgc2)+w1 I), 1 (s*invdeg)@w3Wsn, 2 hs@w5Wgc2
__global__ void k_bake(const float* __restrict__ wmix,
                       const float* __restrict__ Wgcn, const float* __restrict__ Wss,
                       const float* __restrict__ Wsn, const float* __restrict__ Wgin,
                       const float* __restrict__ Wgc1, const float* __restrict__ Wgc2,
                       const float* __restrict__ Wmlp, const float* __restrict__ Wgcnii,
                       __nv_bfloat16* __restrict__ wbT, float* __restrict__ wbF) {
    int s = blockIdx.x;
    int ej = s % 14;
    const float* wv = wmix + ej * 8;
    size_t o = (size_t)s * 4096;
    __nv_bfloat16* obT = wbT + (size_t)s * 4 * 8192;
    float* obF = wbF + (size_t)s * 3 * 4096;
    float w1 = wv[1], w2 = wv[2], w3 = wv[3], w4 = wv[4], w5 = wv[5], w6 = wv[6], w7 = wv[7];
    for (int idx = threadIdx.x; idx < 4096; idx += blockDim.x) {
        int k = idx >> 6, n = idx & 63;
        float tv[4];
        tv[0] = w2 * Wgcn[o + idx];
        tv[1] = w4 * Wgin[o + idx];
        tv[2] = w6 * Wmlp[o + idx];
        tv[3] = w7 * Wgcnii[o + idx];
        for (int p = 0; p < 4; p++) {
            unsigned short hb, lb;
            bsplit(tv[p], hb, lb);
            obT[p * 8192 + idx] = *(__nv_bfloat16*)&hb;
            obT[p * 8192 + 4096 + idx] = *(__nv_bfloat16*)&lb;
        }
        obF[0 * 4096 + idx] = w3 * Wss[o + idx] + w5 * (Wgc1[o + idx] - Wgc2[o + idx]) + ((k == n) ? w1 : 0.f);
        obF[1 * 4096 + idx] = w3 * Wsn[o + idx];
        obF[2 * 4096 + idx] = w5 * Wgc2[o + idx];
    }
}

// ---------------- fp32 tiled GEMM (stem/pre) ----------------
__global__ __launch_bounds__(256) void k_gemm(const float* __restrict__ A, int lda,
                                              const float* __restrict__ B, int ldb,
                                              float* __restrict__ C, int K) {
    __shared__ float As[TS];
    __shared__ float Bs[TS];
    const int tid = threadIdx.x;
    const int m0 = blockIdx.x * 64;
    const int n0b = blockIdx.y * 64;
    const int n0 = (tid & 15) * 4, mm0 = (tid >> 4) * 4;
    float acc[16];
#pragma unroll
    for (int i = 0; i < 16; i++) acc[i] = 0.f;
    for (int kt = 0; kt < K; kt += 64) {
        __syncthreads();
#pragma unroll
        for (int i = 0; i < 16; i++) {
            int idx = tid + i * 256;
            int m = idx >> 6, k = idx & 63;
            int gm = m0 + m;
            As[k * 68 + m] = (gm < NN) ? A[(size_t)gm * lda + kt + k] : 0.f;
            Bs[(idx >> 6) * 68 + (idx & 63)] = B[(size_t)(kt + (idx >> 6)) * ldb + n0b + (idx & 63)];
        }
        __syncthreads();
#pragma unroll 16
        for (int k = 0; k < 64; k++) {
            float4 a4 = *(const float4*)&As[k * 68 + mm0];
            float4 b4 = *(const float4*)&Bs[k * 68 + n0];
            acc[0] += a4.x * b4.x; acc[1] += a4.x * b4.y; acc[2] += a4.x * b4.z; acc[3] += a4.x * b4.w;
            acc[4] += a4.y * b4.x; acc[5] += a4.y * b4.y; acc[6] += a4.y * b4.z; acc[7] += a4.y * b4.w;
            acc[8] += a4.z * b4.x; acc[9] += a4.z * b4.y; acc[10] += a4.z * b4.z; acc[11] += a4.z * b4.w;
            acc[12] += a4.w * b4.x; acc[13] += a4.w * b4.y; acc[14] += a4.w * b4.z; acc[15] += a4.w * b4.w;
        }
    }
#pragma unroll
    for (int r = 0; r < 4; r++) {
        int gm = m0 + mm0 + r;
        if (gm < NN)
            *(float4*)&C[(size_t)gm * ldb + n0b + n0] =
                make_float4(acc[r * 4], acc[r * 4 + 1], acc[r * 4 + 2], acc[r * 4 + 3]);
    }
}

// ---------------- batchnorm + agg ----------------
__global__ void k_colstats(const float* __restrict__ A, int ncols, float* __restrict__ part) {
    int blk = blockIdx.x, c = threadIdx.x;
    int rows_per = (NN + NBLK_STATS - 1) / NBLK_STATS;
    int r0 = blk * rows_per, r1 = min(NN, r0 + rows_per);
    float s = 0.f, s2 = 0.f;
    if (c < ncols)
        for (int r = r0; r < r1; r++) {
            float v = A[(size_t)r * ncols + c];
            s += v; s2 += v * v;
        }
    part[blk * 384 + c] = s;
    part[blk * 384 + 192 + c] = s2;
}
__global__ void k_colfin(const float* __restrict__ part, int ncols, float* __restrict__ stats) {
    int c = threadIdx.x;
    if (c >= ncols) return;
    float s = 0.f, s2 = 0.f;
    for (int b = 0; b < NBLK_STATS; b++) { s += part[b * 384 + c]; s2 += part[b * 384 + 192 + c]; }
    float m = s / (float)NN;
    float v = s2 / (float)NN - m * m;
    stats[c] = m;
    stats[192 + c] = rsqrtf(v + 1e-5f);
}
__global__ void k_bnapply(float* __restrict__ A, int ncols, const float* __restrict__ stats, int dorelu) {
    size_t idx = (size_t)blockIdx.x * blockDim.x + threadIdx.x;
    if (idx >= (size_t)NN * ncols) return;
    int c = (int)(idx % ncols);
    float v = (A[idx] - stats[c]) * stats[192 + c];
    if (dorelu) v = fmaxf(v, 0.f);
    A[idx] = v;
}
__global__ void k_agg(const float* __restrict__ h, int ldh, const int* __restrict__ rowptr,
                      const int* __restrict__ srcs, const float* __restrict__ ew,
                      float* __restrict__ osum, float* __restrict__ onrm) {
    int warp = (blockIdx.x * blockDim.x + threadIdx.x) >> 5;
    if (warp >= NN) return;
    int lane = threadIdx.x & 31;
    int r0 = rowptr[warp], r1 = rowptr[warp + 1];
    float2 s = make_float2(0.f, 0.f), nrm = make_float2(0.f, 0.f);
    for (int p = r0; p < r1; p++) {
        int si = srcs[p];
        float w = ew[p];
        float2 v = *(const float2*)&h[(size_t)si * ldh + lane * 2];
        s.x += v.x; s.y += v.y;
        nrm.x += w * v.x; nrm.y += w * v.y;
    }
    *(float2*)&osum[(size_t)warp * 64 + lane * 2] = s;
    *(float2*)&onrm[(size_t)warp * 64 + lane * 2] = nrm;
}

// ---------------- warp-specialized dual-pipe step kernel ----------------
// warps 0-3: tensor (4 relu panels, bf16 split, fragment accum + RMW epilogue)
// warps 4-5: FFMA (3 lin panels, fp32 exact, 2row x 32col register tile)
__global__ __launch_bounds__(192, 2) void k_step(
    const float* __restrict__ h0p, const float* __restrict__ h1p, const float* __restrict__ h2p,
    const float* __restrict__ h3p, const float* __restrict__ h4p,
    int l0, int l1, int l2, int l3, int l4,
    const float* __restrict__ sums, const float* __restrict__ nrms,
    const float* __restrict__ x0, const float* __restrict__ invdeg,
    const __nv_bfloat16* __restrict__ wbT, const float* __restrict__ wbF,
    int nst, float* __restrict__ outp) {
    extern __shared__ char smc[];
    const u32 sb = s2u(smc);
    const int tid = threadIdx.x, wid = tid >> 5, lane = tid & 31;
    const int m0 = blockIdx.x * 64;
    const bool isT = wid < 4;
    // tensor ids
    const int wrow = wid * 16, fg = lane >> 2, tig = lane & 3;
    // ffma ids
    const int g = tid - 128;                       // 0..63 for ffma warps
    const int fr1 = g >> 1, colb = (g & 1) * 32;   // row in tile, col half
    const int r1g = m0 + fr1, r2g = r1g + 32;
    const bool v1 = !isT && r1g < NN, v2 = !isT && r2g < NN;
    const float idg1 = v1 ? invdeg[r1g] : 0.f;
    const float idg2 = v2 ? invdeg[r2g] : 0.f;

    float acc[64];
#pragma unroll
    for (int i = 0; i < 64; i++) acc[i] = 0.f;   // tensor uses [0..31], ffma all 64

    for (int j = 0; j < nst; j++) {
        const float* h = (j == 0) ? h0p : (j == 1) ? h1p : (j == 2) ? h2p : (j == 3) ? h3p : h4p;
        int ldh = (j == 0) ? l0 : (j == 1) ? l1 : (j == 2) ? l2 : (j == 3) ? l3 : l4;
        const float* ssum = sums + (size_t)j * NSZ;
        const float* snrm = nrms + (size_t)j * NSZ;
        const __nv_bfloat16* wsT = wbT + (size_t)j * 4 * 8192;
        const float* wsF = wbF + (size_t)j * 3 * 4096;

        __syncthreads();  // prev slot fully done reading A tiles
#pragma unroll
        for (int i = 0; i < 6; i++) {   // build bf16 A tiles (all 192 threads)
            int idx = tid + i * 192;
            if (idx < 1024) {
                int row = idx >> 4, cg = (idx & 15) * 4;
                int gm = m0 + row;
                float4 z = make_float4(0.f, 0.f, 0.f, 0.f);
                float4 hv = z, sv = z, nv = z, xv = z;
                if (gm < NN) {
                    hv = *(const float4*)(h + (size_t)gm * ldh + cg);
                    sv = *(const float4*)(ssum + (size_t)gm * 64 + cg);
                    nv = *(const float4*)(snrm + (size_t)gm * 64 + cg);
                    xv = *(const float4*)(x0 + (size_t)gm * 64 + cg);
                }
                float4 hs = make_float4(hv.x + sv.x, hv.y + sv.y, hv.z + sv.z, hv.w + sv.w);
                float4 gv = make_float4(0.9f * nv.x + 0.1f * xv.x, 0.9f * nv.y + 0.1f * xv.y,
                                        0.9f * nv.z + 0.1f * xv.z, 0.9f * nv.w + 0.1f * xv.w);
                int off = row * 144 + cg * 2;
                store_split4(smc + AH + off, smc + AH + 9216 + off, hv);
                store_split4(smc + AHS + off, smc + AHS + 9216 + off, hs);
                store_split4(smc + AN + off, smc + AN + 9216 + off, nv);
                store_split4(smc + AG + off, smc + AG + 9216 + off, gv);
            }
        }
        __syncthreads();  // A ready; groups diverge

        if (isT) {
            // ---------- tensor group: 4 relu panels ----------
#pragma unroll 1
            for (int p = 0; p < 4; p++) {
                BAR_T();  // B buffer free (prev panel mma done)
                const uint4* src = (const uint4*)(wsT + (size_t)p * 8192);
#pragma unroll
                for (int i = 0; i < 8; i++) {
                    int u = tid + i * 128;
                    int rr = u >> 3, c = u & 7;
                    int dst = BOFT + ((rr < 64) ? (rr * 144 + c * 16) : (9216 + (rr - 64) * 144 + c * 16));
                    *(uint4*)(smc + dst) = src[u];
                }
                BAR_T();
                float tc[32];
#pragma unroll
                for (int i = 0; i < 32; i++) tc[i] = 0.f;
                const u32 At = sb + ((p == 0) ? AN : (p == 1) ? AHS : (p == 2) ? AH : AG);
#pragma unroll
                for (int q = 0; q < 4; q++) {
                    u32 aAddr = At + (u32)((wrow + (lane & 7) + ((lane >> 3) & 1) * 8) * 144 + q * 32 + (lane >> 4) * 16);
                    u32 a0, a1, a2, a3, e0, e1, e2, e3;
                    ldsm4(a0, a1, a2, a3, aAddr);
                    ldsm4(e0, e1, e2, e3, aAddr + 9216);
                    u32 bRow = sb + BOFT + (u32)((q * 16 + (lane & 15)) * 144);
#pragma unroll
                    for (int nb = 0; nb < 8; nb++) {
                        u32 b0, b1, c0, c1;
                        ldsm2t(b0, b1, bRow + nb * 16);
                        ldsm2t(c0, c1, bRow + nb * 16 + 9216);
                        mma16816(tc + nb * 4, a0, a1, a2, a3, b0, b1);
                        mma16816(tc + nb * 4, e0, e1, e2, e3, b0, b1);
                        mma16816(tc + nb * 4, a0, a1, a2, a3, c0, c1);
                    }
                }
#pragma unroll
                for (int i = 0; i < 32; i++) acc[i] += fmaxf(tc[i], 0.f);
            }
        } else {
            // ---------- FFMA group: 3 lin panels ----------
            const float* hr1 = h + (size_t)(v1 ? r1g : 0) * ldh;
            const float* hr2 = h + (size_t)(v2 ? r2g : 0) * ldh;
            const float* sr1 = ssum + (size_t)(v1 ? r1g : 0) * 64;
            const float* sr2 = ssum + (size_t)(v2 ? r2g : 0) * 64;
#pragma unroll 1
            for (int p = 0; p < 3; p++) {
                BAR_F();
                {   // publish fp32 panel: 1024 uint4 by 64 threads
                    const uint4* src = (const uint4*)(wsF + (size_t)p * 4096);
                    uint4* dst = (uint4*)(smc + BF);
#pragma unroll
                    for (int i = 0; i < 16; i++) dst[g + i * 64] = src[g + i * 64];
                }
                BAR_F();
                const float* bp = (const float*)(smc + BF) + colb;
#pragma unroll 4
                for (int k4 = 0; k4 < 16; k4++) {
                    int k0 = k4 * 4;
                    float4 a1v, a2v;
                    if (p == 0) {
                        a1v = v1 ? *(const float4*)(hr1 + k0) : make_float4(0, 0, 0, 0);
                        a2v = v2 ? *(const float4*)(hr2 + k0) : make_float4(0, 0, 0, 0);
                    } else if (p == 1) {
                        a1v = v1 ? *(const float4*)(sr1 + k0) : make_float4(0, 0, 0, 0);
                        a2v = v2 ? *(const float4*)(sr2 + k0) : make_float4(0, 0, 0, 0);
                        a1v.x *= idg1; a1v.y *= idg1; a1v.z *= idg1; a1v.w *= idg1;
                        a2v.x *= idg2; a2v.y *= idg2; a2v.z *= idg2; a2v.w *= idg2;
                    } else {
                        float4 u1 = v1 ? *(const float4*)(hr1 + k0) : make_float4(0, 0, 0, 0);
                        float4 w1v = v1 ? *(const float4*)(sr1 + k0) : make_float4(0, 0, 0, 0);
                        float4 u2 = v2 ? *(const float4*)(hr2 + k0) : make_float4(0, 0, 0, 0);
                        float4 w2v = v2 ? *(const float4*)(sr2 + k0) : make_float4(0, 0, 0, 0);
                        a1v = make_float4(u1.x + w1v.x, u1.y + w1v.y, u1.z + w1v.z, u1.w + w1v.w);
                        a2v = make_float4(u2.x + w2v.x, u2.y + w2v.y, u2.z + w2v.z, u2.w + w2v.w);
                    }
#pragma unroll
                    for (int kk = 0; kk < 4; kk++) {
                        float a1 = (kk == 0) ? a1v.x : (kk == 1) ? a1v.y : (kk == 2) ? a1v.z : a1v.w;
                        float a2 = (kk == 0) ? a2v.x : (kk == 1) ? a2v.y : (kk == 2) ? a2v.z : a2v.w;
                        const float* br = bp + (k0 + kk) * 64;
#pragma unroll
                        for (int i2 = 0; i2 < 8; i2++) {
                            float4 b = *(const float4*)(br + i2 * 4);
                            acc[i2 * 4 + 0] += a1 * b.x; acc[i2 * 4 + 1] += a1 * b.y;
                            acc[i2 * 4 + 2] += a1 * b.z; acc[i2 * 4 + 3] += a1 * b.w;
                            acc[32 + i2 * 4 + 0] += a2 * b.x; acc[32 + i2 * 4 + 1] += a2 * b.y;
                            acc[32 + i2 * 4 + 2] += a2 * b.z; acc[32 + i2 * 4 + 3] += a2 * b.w;
                        }
                    }
                }
            }
        }
    }
    // ---- combine: FFMA stores first, tensor RMW after sync ----
    if (!isT) {
        if (v1) {
            float* o1 = outp + (size_t)r1g * 256 + colb;
#pragma unroll
            for (int i = 0; i < 8; i++)
                *(float4*)(o1 + i * 4) = make_float4(acc[i * 4], acc[i * 4 + 1], acc[i * 4 + 2], acc[i * 4 + 3]);
        }
        if (v2) {
            float* o2 = outp + (size_t)r2g * 256 + colb;
#pragma unroll
            for (int i = 0; i < 8; i++)
                *(float4*)(o2 + i * 4) = make_float4(acc[32 + i * 4], acc[32 + i * 4 + 1],
                                                     acc[32 + i * 4 + 2], acc[32 + i * 4 + 3]);
        }
    }
    __syncthreads();
    if (isT) {
        int r0g = m0 + wrow + fg, r1gT = r0g + 8;
#pragma unroll
        for (int nb = 0; nb < 8; nb++) {
            int c = nb * 8 + tig * 2;
            if (r0g < NN) {
                float* p = outp + (size_t)r0g * 256 + c;
                p[0] += acc[nb * 4 + 0];
                p[1] += acc[nb * 4 + 1];
            }
            if (r1gT < NN) {
                float* p = outp + (size_t)r1gT * 256 + c;
                p[0] += acc[nb * 4 + 2];
                p[1] += acc[nb * 4 + 3];
            }
        }
    }
}

__global__ void k_cls(const float* __restrict__ s1, const float* __restrict__ W,
                      const float* __restrict__ b, float* __restrict__ out) {
    int n = blockIdx.x;
    __shared__ float row[256];
    __shared__ float red[64];
    int tid = threadIdx.x;
    float ls = 0.f;
#pragma unroll
    for (int i = 0; i < 4; i++) {
        float v = s1[(size_t)n * 256 + tid + i * 64];
        row[tid + i * 64] = v;
        ls += v;
    }
    red[tid] = ls;
    __syncthreads();
    for (int off = 32; off > 0; off >>= 1) {
        if (tid < off) red[tid] += red[tid + off];
        __syncthreads();
    }
    float pooled = red[0] * (1.0f / 256.0f);
    if (tid < 40) {
        float acc = b[tid] + pooled * W[tid];
#pragma unroll 8
        for (int k = 0; k < 256; k++) acc += row[k] * W[(1 + k) * 40 + tid];
        out[(size_t)n * 40 + tid] = acc;
    }
}

static void bnrun(float* buf, int ncols, int dorelu, float* part, float* stats) {
    k_colstats<<<NBLK_STATS, 192>>>(buf, ncols, part);
    k_colfin<<<1, 192>>>(part, ncols, stats);
    size_t total = (size_t)NN * ncols;
    k_bnapply<<<(int)((total + 255) / 256), 256>>>(buf, ncols, stats, dorelu);
}

extern "C" void kernel_launch(void* const* d_in, const int* in_sizes, int n_in,
                              void* d_out, int out_size) {
    const float* x = (const float*)d_in[0];
    const int* ei = (const int*)d_in[1];
    const float* alphas = (const float*)d_in[2];
    const float* stemW = (const float*)d_in[3];
    const float* preW = (const float*)d_in[4];
    const float* p0W0 = (const float*)d_in[5];
    const float* p1W0 = (const float*)d_in[6];
    const float* p0W1 = (const float*)d_in[7];
    const float* p1W1 = (const float*)d_in[8];
    const float* Wgcn = (const float*)d_in[9];
    const float* Wss = (const float*)d_in[10];
    const float* Wsn = (const float*)d_in[11];
    const float* Wgin = (const float*)d_in[12];
    const float* Wgc1 = (const float*)d_in[13];
    const float* Wgc2 = (const float*)d_in[14];
    const float* Wmlp = (const float*)d_in[15];
    const float* Wgcnii = (const float*)d_in[16];
    const float* clsW = (const float*)d_in[17];
    const float* clsb = (const float*)d_in[18];
    float* out = (float*)d_out;
    const int* srcI = ei;
    const int* dstI = ei + EE;

    float *stem, *x0p, *ap, *bp, *c0, *c1, *sums, *nrms, *wmix, *stats, *part;
    float *invdeg, *invsqrt, *ew, *wbF;
    __nv_bfloat16* wbT;
    int *deg, *cursor, *rowptr, *eid, *srcs, *bsum;
    cudaGetSymbolAddress((void**)&stem, g_stem);
    cudaGetSymbolAddress((void**)&x0p, g_x0);
    cudaGetSymbolAddress((void**)&ap, g_a);
    cudaGetSymbolAddress((void**)&bp, g_b);
    cudaGetSymbolAddress((void**)&c0, g_cell0);
    cudaGetSymbolAddress((void**)&c1, g_cell1);
    cudaGetSymbolAddress((void**)&sums, g_sum);
    cudaGetSymbolAddress((void**)&nrms, g_nrm);
    cudaGetSymbolAddress((void**)&wbT, g_wbkT);
    cudaGetSymbolAddress((void**)&wbF, g_wbkF);
    cudaGetSymbolAddress((void**)&wmix, g_wmix);
    cudaGetSymbolAddress((void**)&stats, g_stats);
    cudaGetSymbolAddress((void**)&part, g_part);
    cudaGetSymbolAddress((void**)&invdeg, g_invdeg);
    cudaGetSymbolAddress((void**)&invsqrt, g_invsqrt);
    cudaGetSymbolAddress((void**)&ew, g_ew);
    cudaGetSymbolAddress((void**)&deg, g_deg);
    cudaGetSymbolAddress((void**)&cursor, g_cursor);
    cudaGetSymbolAddress((void**)&rowptr, g_rowptr);
    cudaGetSymbolAddress((void**)&eid, g_eid);
    cudaGetSymbolAddress((void**)&srcs, g_srcs);
    cudaGetSymbolAddress((void**)&bsum, g_bsum);

    cudaFuncSetAttribute(k_step, cudaFuncAttributeMaxDynamicSharedMemorySize, STEP_SMEM);

    k_zero2<<<(NN + 255) / 256, 256>>>(deg, cursor);
    k_deg<<<(EE + 255) / 256, 256>>>(dstI, deg);
    k_degfin<<<(NN + 255) / 256, 256>>>(deg, invdeg, invsqrt);
    k_scan1<<<SCAN_B, 128>>>(deg, rowptr, bsum);
    k_scan2<<<1, 512>>>(bsum);
    k_scan3<<<(NN + 255) / 256, 256>>>(rowptr, bsum);
    k_scatter<<<(EE + 255) / 256, 256>>>(dstI, rowptr, cursor, eid);
    k_sortfill<<<(NN + 127) / 128, 128>>>(rowptr, eid, srcI, invsqrt, srcs, ew);

    k_softmax<<<1, 16>>>(alphas, wmix);
    k_bake<<<28, 256>>>(wmix, Wgcn, Wss, Wsn, Wgin, Wgc1, Wgc2, Wmlp, Wgcnii, wbT, wbF);

    k_gemm<<<dim3(MT64, 3), 256>>>(x, 128, stemW, 192, stem, 128);
    bnrun(stem, 192, 0, part, stats);
    k_gemm<<<dim3(MT64, 1), 256>>>(x, 128, preW, 64, x0p, 128);
    bnrun(x0p, 64, 1, part, stats);

    const int aggBlocks = (NN * 32 + 255) / 256;
    for (int ci = 0; ci < 2; ci++) {
        const float* s0 = stem; int k0 = 192;
        const float* s1 = (ci == 0) ? stem : c0;
        int k1 = (ci == 0) ? 192 : 256;
        const float* pW0 = (ci == 0) ? p0W0 : p0W1;
        const float* pW1 = (ci == 0) ? p1W0 : p1W1;
        float* cell = (ci == 0) ? c0 : c1;

        k_gemm<<<dim3(MT64, 1), 256>>>(s0, k0, pW0, 64, ap, k0);
        bnrun(ap, 64, 1, part, stats);
        k_gemm<<<dim3(MT64, 1), 256>>>(s1, k1, pW1, 64, bp, k1);
        bnrun(bp, 64, 1, part, stats);

        const float* sp[5] = {ap, bp, cell, cell + 64, cell + 128};
        const int sl[5] = {64, 64, 256, 256, 256};
        k_agg<<<aggBlocks, 256>>>(sp[0], sl[0], rowptr, srcs, ew, sums, nrms);
        k_agg<<<aggBlocks, 256>>>(sp[1], sl[1], rowptr, srcs, ew, sums + (size_t)NSZ, nrms + (size_t)NSZ);

        int ej0 = 0;
        for (int t = 0; t < 4; t++) {
            int slot0 = ci * 14 + ej0;
            k_step<<<MT64, 192, STEP_SMEM>>>(sp[0], sp[1], sp[2], sp[3], sp[4],
                                             sl[0], sl[1], sl[2], sl[3], sl[4],
                                             sums, nrms, x0p, invdeg,
                                             wbT + (size_t)slot0 * 4 * 8192,
                                             wbF + (size_t)slot0 * 3 * 4096,
                                             t + 2, cell + t * 64);
            ej0 += t + 2;
            if (t < 3) {
                int ns = t + 2;
                k_agg<<<aggBlocks, 256>>>(sp[ns], sl[ns], rowptr, srcs, ew,
                                          sums + (size_t)ns * NSZ, nrms + (size_t)ns * NSZ);
            }
        }
    }
    k_cls<<<NN, 64>>>(c1, clsW, clsb, out);
}

// round 13
// speedup vs baseline: 1.6782x; 1.4200x over previous
#include <cuda_runtime.h>
#include <cuda_bf16.h>
#include <mma.h>
#include <math.h>
using namespace nvcuda;

#define NN 50000
#define EE 800000
#define MT64 ((NN + 63) / 64)
#define NSZ (NN * 64)
#define SCAN_B ((NN + 127) / 128)
#define TS 4352
typedef unsigned int u32;

#define AH 0
#define AHS 18432
#define AN 36864
#define AG 55296
#define BOF 73728
#define CST 92160
#define STEP_SMEM 109568
#define PGRID 304

__device__ __forceinline__ void bsplit(float x, unsigned short& hb, unsigned short& lb) {
    __nv_bfloat16 h = __float2bfloat16_rn(x);
    float r = x - __bfloat162float(h);
    __nv_bfloat16 l = __float2bfloat16_rn(r);
    hb = *(unsigned short*)&h;
    lb = *(unsigned short*)&l;
}
__device__ __forceinline__ void store_split4(char* hp, char* lp, float4 v) {
    unsigned short h0, l0, h1, l1, h2, l2, h3, l3;
    bsplit(v.x, h0, l0); bsplit(v.y, h1, l1); bsplit(v.z, h2, l2); bsplit(v.w, h3, l3);
    *(uint2*)hp = make_uint2(((u32)h1 << 16) | h0, ((u32)h3 << 16) | h2);
    *(uint2*)lp = make_uint2(((u32)l1 << 16) | l0, ((u32)l3 << 16) | l2);
}

__device__ float g_stem[(size_t)NN * 192];
__device__ float g_x0[(size_t)NN * 64];
__device__ float g_a[(size_t)NN * 64];
__device__ float g_b[(size_t)NN * 64];
__device__ float g_cell0[(size_t)NN * 256];
__device__ float g_cell1[(size_t)NN * 256];
__device__ float g_sum[(size_t)5 * NSZ];
__device__ float g_nrm[(size_t)5 * NSZ];
__device__ __nv_bfloat16 g_wbk[(size_t)28 * 8 * 8192];
__device__ float g_wmix[14 * 8];
__device__ float g_stats[384];
__device__ float g_part[(size_t)MT64 * 3 * 384];
__device__ float g_invdeg[NN];
__device__ float g_invsqrt[NN];
__device__ float g_ew[EE];
__device__ int g_deg[NN];
__device__ int g_cursor[NN];
__device__ int g_rowptr[NN + 1];
__device__ int g_eid[EE];
__device__ int g_srcs[EE];
__device__ int g_bsum[512];

// ---------------- CSR ----------------
__global__ void k_zero2(int* a, int* b) {
    int i = blockIdx.x * blockDim.x + threadIdx.x;
    if (i < NN) { a[i] = 0; b[i] = 0; }
}
__global__ void k_deg(const int* __restrict__ dst, int* __restrict__ deg) {
    int e = blockIdx.x * blockDim.x + threadIdx.x;
    if (e < EE) atomicAdd(&deg[dst[e]], 1);
}
__global__ void k_degfin(const int* __restrict__ deg, float* __restrict__ invdeg,
                         float* __restrict__ invsqrt) {
    int i = blockIdx.x * blockDim.x + threadIdx.x;
    if (i < NN) {
        float d = (float)max(deg[i], 1);
        invdeg[i] = 1.0f / d;
        invsqrt[i] = rsqrtf(d);
    }
}
__global__ void k_scan1(const int* __restrict__ deg, int* __restrict__ rowptr, int* __restrict__ bsum) {
    __shared__ int s[128];
    int b = blockIdx.x, t = threadIdx.x;
    int i = b * 128 + t;
    int v = (i < NN) ? deg[i] : 0;
    s[t] = v;
    __syncthreads();
    for (int off = 1; off < 128; off <<= 1) {
        int u = (t >= off) ? s[t - off] : 0;
        __syncthreads();
        s[t] += u;
        __syncthreads();
    }
    if (i < NN) rowptr[i] = s[t] - v;
    if (t == 127) bsum[b] = s[127];
}
__global__ void k_scan2(int* __restrict__ bsum) {
    __shared__ int s[512];
    int t = threadIdx.x;
    int v = (t < SCAN_B) ? bsum[t] : 0;
    s[t] = v;
    __syncthreads();
    for (int off = 1; off < 512; off <<= 1) {
        int u = (t >= off) ? s[t - off] : 0;
        __syncthreads();
        s[t] += u;
        __syncthreads();
    }
    if (t < SCAN_B) bsum[t] = s[t] - v;
}
__global__ void k_scan3(int* __restrict__ rowptr, const int* __restrict__ bsum) {
    int i = blockIdx.x * blockDim.x + threadIdx.x;
    if (i < NN) rowptr[i] += bsum[i >> 7];
    if (i == 0) rowptr[NN] = EE;
}
__global__ void k_scatter(const int* __restrict__ dst, const int* __restrict__ rowptr,
                          int* __restrict__ cursor, int* __restrict__ eid) {
    int e = blockIdx.x * blockDim.x + threadIdx.x;
    if (e < EE) {
        int d = dst[e];
        int pos = rowptr[d] + atomicAdd(&cursor[d], 1);
        eid[pos] = e;
    }
}
__global__ void k_sortfill(const int* __restrict__ rowptr, int* __restrict__ eid,
                           const int* __restrict__ src, const float* __restrict__ invsqrt,
                           int* __restrict__ srcs, float* __restrict__ ew) {
    int n = blockIdx.x * blockDim.x + threadIdx.x;
    if (n >= NN) return;
    int r0 = rowptr[n], r1 = rowptr[n + 1];
    for (int i = r0 + 1; i < r1; i++) {
        int key = eid[i];
        int j = i - 1;
        while (j >= r0 && eid[j] > key) { eid[j + 1] = eid[j]; j--; }
        eid[j + 1] = key;
    }
    float isd = invsqrt[n];
    for (int p = r0; p < r1; p++) {
        int e = eid[p];
        int s = src[e];
        srcs[p] = s;
        ew[p] = invsqrt[s] * isd;
    }
}
__global__ void k_softmax(const float* __restrict__ alphas, float* __restrict__ wmix) {
    int r = threadIdx.x;
    if (r >= 14) return;
    float m = -1e30f;
    for (int o = 0; o < 8; o++) m = fmaxf(m, alphas[r * 8 + o]);
    float e[8], s = 0.f;
    for (int o = 0; o < 8; o++) { e[o] = expf(alphas[r * 8 + o] - m); s += e[o]; }
    float inv = 1.0f / s;
    for (int o = 0; o < 8; o++) wmix[r * 8 + o] = e[o] * inv;
}

// bake 8 bf16-split B panels/slot. A sources: p0:h p1:hs p2:hs p3:h p4:norm p5:hs p6:h p7:gmix
__global__ void k_bake(const float* __restrict__ wmix,
                       const float* __restrict__ Wgcn, const float* __restrict__ Wss,
                       const float* __restrict__ Wsn, const float* __restrict__ Wgin,
                       const float* __restrict__ Wgc1, const float* __restrict__ Wgc2,
                       const float* __restrict__ Wmlp, const float* __restrict__ Wgcnii,
                       __nv_bfloat16* __restrict__ wbk) {
    int s = blockIdx.x;
    int ej = s % 14;
    const float* wv = wmix + ej * 8;
    size_t o = (size_t)s * 4096;
    __nv_bfloat16* ob = wbk + (size_t)s * 8 * 8192;
    float w1 = wv[1], w2 = wv[2], w3 = wv[3], w4 = wv[4], w5 = wv[5], w6 = wv[6], w7 = wv[7];
    for (int idx = threadIdx.x; idx < 4096; idx += blockDim.x) {
        int k = idx >> 6, n = idx & 63;
        for (int p = 0; p < 8; p++) {
            float v;
            if (p == 0) v = w3 * Wss[o + idx] + w5 * (Wgc1[o + idx] - Wgc2[o + idx]) + ((k == n) ? w1 : 0.f);
            else if (p == 1) v = w5 * Wgc2[o + idx];
            else if (p == 2) v = w3 * Wsn[o + idx];
            else if (p == 3) v = -w3 * Wsn[o + idx];
            else if (p == 4) v = w2 * Wgcn[o + idx];
            else if (p == 5) v = w4 * Wgin[o + idx];
            else if (p == 6) v = w6 * Wmlp[o + idx];
            else v = w7 * Wgcnii[o + idx];
            unsigned short hb, lb;
            bsplit(v, hb, lb);
            ob[p * 8192 + idx] = *(__nv_bfloat16*)&hb;
            ob[p * 8192 + 4096 + idx] = *(__nv_bfloat16*)&lb;
        }
    }
}

// ---------------- fp32 tiled GEMM with fused BN column partials ----------------
__global__ __launch_bounds__(256) void k_gemm(const float* __restrict__ A, int lda,
                                              const float* __restrict__ B, int ldb,
                                              float* __restrict__ C, int K,
                                              float* __restrict__ part) {
    __shared__ float As[TS];
    __shared__ float Bs[TS];
    const int tid = threadIdx.x;
    const int m0 = blockIdx.x * 64;
    const int n0b = blockIdx.y * 64;
    const int tx = tid & 15, ty = tid >> 4;
    const int n0 = tx * 4, mm0 = ty * 4;
    float acc[16];
#pragma unroll
    for (int i = 0; i < 16; i++) acc[i] = 0.f;
    for (int kt = 0; kt < K; kt += 64) {
        __syncthreads();
#pragma unroll
        for (int i = 0; i < 16; i++) {
            int idx = tid + i * 256;
            int m = idx >> 6, k = idx & 63;
            int gm = m0 + m;
            As[k * 68 + m] = (gm < NN) ? A[(size_t)gm * lda + kt + k] : 0.f;
            Bs[(idx >> 6) * 68 + (idx & 63)] = B[(size_t)(kt + (idx >> 6)) * ldb + n0b + (idx & 63)];
        }
        __syncthreads();
#pragma unroll 16
        for (int k = 0; k < 64; k++) {
            float4 a4 = *(const float4*)&As[k * 68 + mm0];
            float4 b4 = *(const float4*)&Bs[k * 68 + n0];
            acc[0] += a4.x * b4.x; acc[1] += a4.x * b4.y; acc[2] += a4.x * b4.z; acc[3] += a4.x * b4.w;
            acc[4] += a4.y * b4.x; acc[5] += a4.y * b4.y; acc[6] += a4.y * b4.z; acc[7] += a4.y * b4.w;
            acc[8] += a4.z * b4.x; acc[9] += a4.z * b4.y; acc[10] += a4.z * b4.z; acc[11] += a4.z * b4.w;
            acc[12] += a4.w * b4.x; acc[13] += a4.w * b4.y; acc[14] += a4.w * b4.z; acc[15] += a4.w * b4.w;
        }
    }
#pragma unroll
    for (int r = 0; r < 4; r++) {
        int gm = m0 + mm0 + r;
        if (gm < NN)
            *(float4*)&C[(size_t)gm * ldb + n0b + n0] =
                make_float4(acc[r * 4], acc[r * 4 + 1], acc[r * 4 + 2], acc[r * 4 + 3]);
    }
    // fused BN column partials (deterministic per-block)
    __syncthreads();
#pragma unroll
    for (int c = 0; c < 4; c++) {
        float s = 0.f, q = 0.f;
#pragma unroll
        for (int r = 0; r < 4; r++) {
            if (m0 + mm0 + r < NN) { float v = acc[r * 4 + c]; s += v; q += v * v; }
        }
        As[ty * 64 + n0 + c] = s;
        Bs[ty * 64 + n0 + c] = q;
    }
    __syncthreads();
    if (ty == 0) {
        int blkid = blockIdx.x * gridDim.y + blockIdx.y;
#pragma unroll
        for (int c = 0; c < 4; c++) {
            float s = 0.f, q = 0.f;
#pragma unroll
            for (int t = 0; t < 16; t++) { s += As[t * 64 + n0 + c]; q += Bs[t * 64 + n0 + c]; }
            part[(size_t)blkid * 384 + n0b + n0 + c] = s;
            part[(size_t)blkid * 384 + 192 + n0b + n0 + c] = q;
        }
    }
}

__global__ void k_colfin(const float* __restrict__ part, int ny, float* __restrict__ stats) {
    int c = blockIdx.x, t = threadIdx.x;
    int by = c >> 6;
    float s = 0.f, q = 0.f;
    for (int bx = t; bx < MT64; bx += 256) {
        size_t blk = (size_t)(bx * ny + by) * 384;
        s += part[blk + c];
        q += part[blk + 192 + c];
    }
    __shared__ float rs[256], rq[256];
    rs[t] = s; rq[t] = q;
    __syncthreads();
    for (int o = 128; o > 0; o >>= 1) {
        if (t < o) { rs[t] += rs[t + o]; rq[t] += rq[t + o]; }
        __syncthreads();
    }
    if (t == 0) {
        float m = rs[0] / (float)NN;
        float v = rq[0] / (float)NN - m * m;
        stats[c] = m;
        stats[192 + c] = rsqrtf(v + 1e-5f);
    }
}
__global__ void k_bnapply(float* __restrict__ A, int ncols, const float* __restrict__ stats, int dorelu) {
    size_t idx = (size_t)blockIdx.x * blockDim.x + threadIdx.x;
    if (idx >= (size_t)NN * ncols) return;
    int c = (int)(idx % ncols);
    float v = (A[idx] - stats[c]) * stats[192 + c];
    if (dorelu) v = fmaxf(v, 0.f);
    A[idx] = v;
}
__global__ void k_agg(const float* __restrict__ h, int ldh, const int* __restrict__ rowptr,
                      const int* __restrict__ srcs, const float* __restrict__ ew,
                      float* __restrict__ osum, float* __restrict__ onrm) {
    int warp = (blockIdx.x * blockDim.x + threadIdx.x) >> 5;
    if (warp >= NN) return;
    int lane = threadIdx.x & 31;
    int r0 = rowptr[warp], r1 = rowptr[warp + 1];
    float2 s = make_float2(0.f, 0.f), nrm = make_float2(0.f, 0.f);
    for (int p = r0; p < r1; p++) {
        int si = srcs[p];
        float w = ew[p];
        float2 v = *(const float2*)&h[(size_t)si * ldh + lane * 2];
        s.x += v.x; s.y += v.y;
        nrm.x += w * v.x; nrm.y += w * v.y;
    }
    *(float2*)&osum[(size_t)warp * 64 + lane * 2] = s;
    *(float2*)&onrm[(size_t)warp * 64 + lane * 2] = nrm;
}
// paired aggregation for the two cell-input states (shared index/weight reads)
__global__ void k_agg2(const float* __restrict__ h0, int l0, const float* __restrict__ h1, int l1,
                       const int* __restrict__ rowptr, const int* __restrict__ srcs,
                       const float* __restrict__ ew,
                       float* __restrict__ sums, float* __restrict__ nrms) {
    int warp = (blockIdx.x * blockDim.x + threadIdx.x) >> 5;
    if (warp >= NN) return;
    int lane = threadIdx.x & 31;
    int r0 = rowptr[warp], r1 = rowptr[warp + 1];
    float2 s0 = make_float2(0.f, 0.f), n0 = make_float2(0.f, 0.f);
    float2 s1 = make_float2(0.f, 0.f), n1 = make_float2(0.f, 0.f);
    for (int p = r0; p < r1; p++) {
        int si = srcs[p];
        float w = ew[p];
        float2 v0 = *(const float2*)&h0[(size_t)si * l0 + lane * 2];
        float2 v1 = *(const float2*)&h1[(size_t)si * l1 + lane * 2];
        s0.x += v0.x; s0.y += v0.y; n0.x += w * v0.x; n0.y += w * v0.y;
        s1.x += v1.x; s1.y += v1.y; n1.x += w * v1.x; n1.y += w * v1.y;
    }
    size_t o = (size_t)warp * 64 + lane * 2;
    *(float2*)&sums[o] = s0;
    *(float2*)&nrms[o] = n0;
    *(float2*)&sums[NSZ + o] = s1;
    *(float2*)&nrms[NSZ + o] = n1;
}

// ---------------- persistent wmma bf16-split step kernel (round-9 core) ----------------
typedef wmma::fragment<wmma::matrix_a, 16, 16, 16, __nv_bfloat16, wmma::row_major> FragA;
typedef wmma::fragment<wmma::matrix_b, 16, 16, 16, __nv_bfloat16, wmma::row_major> FragB;
typedef wmma::fragment<wmma::accumulator, 16, 16, 16, float> FragC;

__global__ __launch_bounds__(128, 2) void k_step(
    const float* __restrict__ h0p, const float* __restrict__ h1p, const float* __restrict__ h2p,
    const float* __restrict__ h3p, const float* __restrict__ h4p,
    int l0, int l1, int l2, int l3, int l4,
    const float* __restrict__ sums, const float* __restrict__ nrms,
    const float* __restrict__ x0, const float* __restrict__ invdeg,
    const __nv_bfloat16* __restrict__ wbase, int nst, float* __restrict__ outp) {
    extern __shared__ char smc[];
    const int tid = threadIdx.x, wid = tid >> 5, lane = tid & 31;
    const int wrow = wid * 16;
    float* cst = (float*)(smc + CST + wid * 4352);
    const int pa[8] = {AH, AHS, AHS, AH, AN, AHS, AH, AG};
    const int fillf[8] = {1, 0, 1, 0, 1, 1, 1, 1};
    const int epi[8] = {-1, 0, -1, 1, 2, 2, 2, 2};

    for (int m0 = blockIdx.x * 64; m0 < NN; m0 += gridDim.x * 64) {
        const int mE = m0 + wrow + (lane >> 1);
        const float idg = (mE < NN) ? invdeg[mE] : 0.f;
        float outv[32];
#pragma unroll
        for (int i = 0; i < 32; i++) outv[i] = 0.f;
        FragC fc[4];
        uint4 pf[8];
        {
            const uint4* s = (const uint4*)wbase;
#pragma unroll
            for (int i = 0; i < 8; i++) pf[i] = s[tid + i * 128];
        }

        for (int j = 0; j < nst; j++) {
            const float* h = (j == 0) ? h0p : (j == 1) ? h1p : (j == 2) ? h2p : (j == 3) ? h3p : h4p;
            int ldh = (j == 0) ? l0 : (j == 1) ? l1 : (j == 2) ? l2 : (j == 3) ? l3 : l4;
            const float* ssum = sums + (size_t)j * NSZ;
            const float* snrm = nrms + (size_t)j * NSZ;
            const __nv_bfloat16* wslot = wbase + (size_t)j * 8 * 8192;

            __syncthreads();
#pragma unroll
            for (int i = 0; i < 8; i++) {
                int idx = tid + i * 128;
                int row = idx >> 4, cg = (idx & 15) * 4;
                int gm = m0 + row;
                float4 z = make_float4(0.f, 0.f, 0.f, 0.f);
                float4 hv = z, sv = z, nv = z, xv = z;
                if (gm < NN) {
                    hv = *(const float4*)(h + (size_t)gm * ldh + cg);
                    sv = *(const float4*)(ssum + (size_t)gm * 64 + cg);
                    nv = *(const float4*)(snrm + (size_t)gm * 64 + cg);
                    xv = *(const float4*)(x0 + (size_t)gm * 64 + cg);
                }
                float4 hs = make_float4(hv.x + sv.x, hv.y + sv.y, hv.z + sv.z, hv.w + sv.w);
                float4 gv = make_float4(0.9f * nv.x + 0.1f * xv.x, 0.9f * nv.y + 0.1f * xv.y,
                                        0.9f * nv.z + 0.1f * xv.z, 0.9f * nv.w + 0.1f * xv.w);
                int off = row * 144 + cg * 2;
                store_split4(smc + AH + off, smc + AH + 9216 + off, hv);
                store_split4(smc + AHS + off, smc + AHS + 9216 + off, hs);
                store_split4(smc + AN + off, smc + AN + 9216 + off, nv);
                store_split4(smc + AG + off, smc + AG + 9216 + off, gv);
            }

            for (int p = 0; p < 8; p++) {
                __syncthreads();
#pragma unroll
                for (int i = 0; i < 8; i++) {
                    int u = tid + i * 128;
                    int r = u >> 3, c = u & 7;
                    int dst = BOF + ((r < 64) ? (r * 144 + c * 16) : (9216 + (r - 64) * 144 + c * 16));
                    *(uint4*)(smc + dst) = pf[i];
                }
                __syncthreads();
                if (p < 7 || j + 1 < nst) {
                    const uint4* s = (const uint4*)(wslot + (size_t)(p + 1) * 8192);
#pragma unroll
                    for (int i = 0; i < 8; i++) pf[i] = s[tid + i * 128];
                }
                if (fillf[p]) {
#pragma unroll
                    for (int nf = 0; nf < 4; nf++) wmma::fill_fragment(fc[nf], 0.f);
                }
                const __nv_bfloat16* BH = (const __nv_bfloat16*)(smc + BOF);
                const __nv_bfloat16* BL = BH + 4608;
                const __nv_bfloat16* A0 = (const __nv_bfloat16*)(smc + pa[p]) + wrow * 72;
#pragma unroll
                for (int kc = 0; kc < 4; kc++) {
                    FragB bh[4], bl[4];
#pragma unroll
                    for (int nf = 0; nf < 4; nf++) {
                        wmma::load_matrix_sync(bh[nf], BH + kc * 1152 + nf * 16, 72);
                        wmma::load_matrix_sync(bl[nf], BL + kc * 1152 + nf * 16, 72);
                    }
                    FragA fa;
                    wmma::load_matrix_sync(fa, A0 + kc * 16, 72);
#pragma unroll
                    for (int nf = 0; nf < 4; nf++) wmma::mma_sync(fc[nf], fa, bh[nf], fc[nf]);
#pragma unroll
                    for (int nf = 0; nf < 4; nf++) wmma::mma_sync(fc[nf], fa, bl[nf], fc[nf]);
                    wmma::load_matrix_sync(fa, A0 + 4608 + kc * 16, 72);
#pragma unroll
                    for (int nf = 0; nf < 4; nf++) wmma::mma_sync(fc[nf], fa, bh[nf], fc[nf]);
                }
                int e = epi[p];
                if (e >= 0) {
#pragma unroll
                    for (int nf = 0; nf < 4; nf++)
                        wmma::store_matrix_sync(cst + nf * 16, fc[nf], 68, wmma::mem_row_major);
                    __syncwarp();
                    const float4* rp = (const float4*)(cst + (lane >> 1) * 68 + (lane & 1) * 32);
#pragma unroll
                    for (int i = 0; i < 8; i++) {
                        float4 v = rp[i];
                        if (e == 1) { v.x *= idg; v.y *= idg; v.z *= idg; v.w *= idg; }
                        else if (e == 2) {
                            v.x = fmaxf(v.x, 0.f); v.y = fmaxf(v.y, 0.f);
                            v.z = fmaxf(v.z, 0.f); v.w = fmaxf(v.w, 0.f);
                        }
                        outv[i * 4 + 0] += v.x; outv[i * 4 + 1] += v.y;
                        outv[i * 4 + 2] += v.z; outv[i * 4 + 3] += v.w;
                    }
                    __syncwarp();
                }
            }
        }
        if (mE < NN) {
            float* orow = outp + (size_t)mE * 256 + (lane & 1) * 32;
#pragma unroll
            for (int i = 0; i < 8; i++)
                *(float4*)(orow + i * 4) =
                    make_float4(outv[i * 4], outv[i * 4 + 1], outv[i * 4 + 2], outv[i * 4 + 3]);
        }
    }
}

__global__ void k_cls(const float* __restrict__ s1, const float* __restrict__ W,
                      const float* __restrict__ b, float* __restrict__ out) {
    int n = blockIdx.x;
    __shared__ float row[256];
    __shared__ float red[64];
    int tid = threadIdx.x;
    float ls = 0.f;
#pragma unroll
    for (int i = 0; i < 4; i++) {
        float v = s1[(size_t)n * 256 + tid + i * 64];
        row[tid + i * 64] = v;
        ls += v;
    }
    red[tid] = ls;
    __syncthreads();
    for (int off = 32; off > 0; off >>= 1) {
        if (tid < off) red[tid] += red[tid + off];
        __syncthreads();
    }
    float pooled = red[0] * (1.0f / 256.0f);
    if (tid < 40) {
        float acc = b[tid] + pooled * W[tid];
#pragma unroll 8
        for (int k = 0; k < 256; k++) acc += row[k] * W[(1 + k) * 40 + tid];
        out[(size_t)n * 40 + tid] = acc;
    }
}

static void bnrun(float* buf, int ncols, int ny, int dorelu, float* part, float* stats) {
    k_colfin<<<ncols, 256>>>(part, ny, stats);
    size_t total = (size_t)NN * ncols;
    k_bnapply<<<(int)((total + 255) / 256), 256>>>(buf, ncols, stats, dorelu);
}

extern "C" void kernel_launch(void* const* d_in, const int* in_sizes, int n_in,
                              void* d_out, int out_size) {
    const float* x = (const float*)d_in[0];
    const int* ei = (const int*)d_in[1];
    const float* alphas = (const float*)d_in[2];
    const float* stemW = (const float*)d_in[3];
    const float* preW = (const float*)d_in[4];
    const float* p0W0 = (const float*)d_in[5];
    const float* p1W0 = (const float*)d_in[6];
    const float* p0W1 = (const float*)d_in[7];
    const float* p1W1 = (const float*)d_in[8];
    const float* Wgcn = (const float*)d_in[9];
    const float* Wss = (const float*)d_in[10];
    const float* Wsn = (const float*)d_in[11];
    const float* Wgin = (const float*)d_in[12];
    const float* Wgc1 = (const float*)d_in[13];
    const float* Wgc2 = (const float*)d_in[14];
    const float* Wmlp = (const float*)d_in[15];
    const float* Wgcnii = (const float*)d_in[16];
    const float* clsW = (const float*)d_in[17];
    const float* clsb = (const float*)d_in[18];
    float* out = (float*)d_out;
    const int* srcI = ei;
    const int* dstI = ei + EE;

    float *stem, *x0p, *ap, *bp, *c0, *c1, *sums, *nrms, *wmix, *stats, *part;
    float *invdeg, *invsqrt, *ew;
    __nv_bfloat16* wbk;
    int *deg, *cursor, *rowptr, *eid, *srcs, *bsum;
    cudaGetSymbolAddress((void**)&stem, g_stem);
    cudaGetSymbolAddress((void**)&x0p, g_x0);
    cudaGetSymbolAddress((void**)&ap, g_a);
    cudaGetSymbolAddress((void**)&bp, g_b);
    cudaGetSymbolAddress((void**)&c0, g_cell0);
    cudaGetSymbolAddress((void**)&c1, g_cell1);
    cudaGetSymbolAddress((void**)&sums, g_sum);
    cudaGetSymbolAddress((void**)&nrms, g_nrm);
    cudaGetSymbolAddress((void**)&wbk, g_wbk);
    cudaGetSymbolAddress((void**)&wmix, g_wmix);
    cudaGetSymbolAddress((void**)&stats, g_stats);
    cudaGetSymbolAddress((void**)&part, g_part);
    cudaGetSymbolAddress((void**)&invdeg, g_invdeg);
    cudaGetSymbolAddress((void**)&invsqrt, g_invsqrt);
    cudaGetSymbolAddress((void**)&ew, g_ew);
    cudaGetSymbolAddress((void**)&deg, g_deg);
    cudaGetSymbolAddress((void**)&cursor, g_cursor);
    cudaGetSymbolAddress((void**)&rowptr, g_rowptr);
    cudaGetSymbolAddress((void**)&eid, g_eid);
    cudaGetSymbolAddress((void**)&srcs, g_srcs);
    cudaGetSymbolAddress((void**)&bsum, g_bsum);

    cudaFuncSetAttribute(k_step, cudaFuncAttributeMaxDynamicSharedMemorySize, STEP_SMEM);

    k_zero2<<<(NN + 255) / 256, 256>>>(deg, cursor);
    k_deg<<<(EE + 255) / 256, 256>>>(dstI, deg);
    k_degfin<<<(NN + 255) / 256, 256>>>(deg, invdeg, invsqrt);
    k_scan1<<<SCAN_B, 128>>>(deg, rowptr, bsum);
    k_scan2<<<1, 512>>>(bsum);
    k_scan3<<<(NN + 255) / 256, 256>>>(rowptr, bsum);
    k_scatter<<<(EE + 255) / 256, 256>>>(dstI, rowptr, cursor, eid);
    k_sortfill<<<(NN + 127) / 128, 128>>>(rowptr, eid, srcI, invsqrt, srcs, ew);

    k_softmax<<<1, 16>>>(alphas, wmix);
    k_bake<<<28, 256>>>(wmix, Wgcn, Wss, Wsn, Wgin, Wgc1, Wgc2, Wmlp, Wgcnii, wbk);

    k_gemm<<<dim3(MT64, 3), 256>>>(x, 128, stemW, 192, stem, 128, part);
    bnrun(stem, 192, 3, 0, part, stats);
    k_gemm<<<dim3(MT64, 1), 256>>>(x, 128, preW, 64, x0p, 128, part);
    bnrun(x0p, 64, 1, 1, part, stats);

    const int aggBlocks = (NN * 32 + 255) / 256;
    for (int ci = 0; ci < 2; ci++) {
        const float* s0 = stem; int k0 = 192;
        const float* s1 = (ci == 0) ? stem : c0;
        int k1 = (ci == 0) ? 192 : 256;
        const float* pW0 = (ci == 0) ? p0W0 : p0W1;
        const float* pW1 = (ci == 0) ? p1W0 : p1W1;
        float* cell = (ci == 0) ? c0 : c1;

        k_gemm<<<dim3(MT64, 1), 256>>>(s0, k0, pW0, 64, ap, k0, part);
        bnrun(ap, 64, 1, 1, part, stats);
        k_gemm<<<dim3(MT64, 1), 256>>>(s1, k1, pW1, 64, bp, k1, part);
        bnrun(bp, 64, 1, 1, part, stats);

        const float* sp[5] = {ap, bp, cell, cell + 64, cell + 128};
        const int sl[5] = {64, 64, 256, 256, 256};
        k_agg2<<<aggBlocks, 256>>>(sp[0], sl[0], sp[1], sl[1], rowptr, srcs, ew, sums, nrms);

        int ej0 = 0;
        for (int t = 0; t < 4; t++) {
            const __nv_bfloat16* wb = wbk + (size_t)(ci * 14 + ej0) * 8 * 8192;
            k_step<<<PGRID, 128, STEP_SMEM>>>(sp[0], sp[1], sp[2], sp[3], sp[4],
                                              sl[0], sl[1], sl[2], sl[3], sl[4],
                                              sums, nrms, x0p, invdeg, wb, t + 2, cell + t * 64);
            ej0 += t + 2;
            if (t < 3) {
                int ns = t + 2;
                k_agg<<<aggBlocks, 256>>>(sp[ns], sl[ns], rowptr, srcs, ew,
                                          sums + (size_t)ns * NSZ, nrms + (size_t)ns * NSZ);
            }
        }
    }
    k_cls<<<NN, 64>>>(c1, clsW, clsb, out);
}

// round 14
// speedup vs baseline: 2.1141x; 1.2598x over previous
#include <cuda_runtime.h>
#include <cuda_bf16.h>
#include <math.h>

#define NN 50000
#define EE 800000
#define MT64 ((NN + 63) / 64)
#define NSZ (NN * 64)
#define SCAN_B ((NN + 127) / 128)
#define TS 4352
typedef unsigned int u32;

// k_step smem: 5 bf16 A tiles (64r x 72 stride; hi 9216 + lo 9216 each) + B
#define AH 0
#define AHS 18432
#define AM 36864
#define AN 55296
#define AG 73728
#define BOF 92160
#define STEP_SMEM 110592
#define PGRID 304

__device__ __forceinline__ u32 s2u(const void* p) {
    u32 a;
    asm("{ .reg .u64 t; cvta.to.shared.u64 t, %1; cvt.u32.u64 %0, t; }" : "=r"(a) : "l"(p));
    return a;
}
__device__ __forceinline__ void ldsm4(u32& r0, u32& r1, u32& r2, u32& r3, u32 a) {
    asm volatile("ldmatrix.sync.aligned.m8n8.x4.shared.b16 {%0,%1,%2,%3}, [%4];"
                 : "=r"(r0), "=r"(r1), "=r"(r2), "=r"(r3) : "r"(a));
}
__device__ __forceinline__ void ldsm2t(u32& r0, u32& r1, u32 a) {
    asm volatile("ldmatrix.sync.aligned.m8n8.x2.trans.shared.b16 {%0,%1}, [%2];"
                 : "=r"(r0), "=r"(r1) : "r"(a));
}
__device__ __forceinline__ void mma16816(float* c, u32 a0, u32 a1, u32 a2, u32 a3, u32 b0, u32 b1) {
    asm volatile("mma.sync.aligned.m16n8k16.row.col.f32.bf16.bf16.f32 "
                 "{%0,%1,%2,%3}, {%4,%5,%6,%7}, {%8,%9}, {%0,%1,%2,%3};"
                 : "+f"(c[0]), "+f"(c[1]), "+f"(c[2]), "+f"(c[3])
                 : "r"(a0), "r"(a1), "r"(a2), "r"(a3), "r"(b0), "r"(b1));
}
__device__ __forceinline__ void bsplit(float x, unsigned short& hb, unsigned short& lb) {
    __nv_bfloat16 h = __float2bfloat16_rn(x);
    float r = x - __bfloat162float(h);
    __nv_bfloat16 l = __float2bfloat16_rn(r);
    hb = *(unsigned short*)&h;
    lb = *(unsigned short*)&l;
}
__device__ __forceinline__ void store_split4(char* hp, char* lp, float4 v) {
    unsigned short h0, l0, h1, l1, h2, l2, h3, l3;
    bsplit(v.x, h0, l0); bsplit(v.y, h1, l1); bsplit(v.z, h2, l2); bsplit(v.w, h3, l3);
    *(uint2*)hp = make_uint2(((u32)h1 << 16) | h0, ((u32)h3 << 16) | h2);
    *(uint2*)lp = make_uint2(((u32)l1 << 16) | l0, ((u32)l3 << 16) | l2);
}

__device__ float g_stem[(size_t)NN * 192];
__device__ float g_x0[(size_t)NN * 64];
__device__ float g_a[(size_t)NN * 64];
__device__ float g_b[(size_t)NN * 64];
__device__ float g_cell0[(size_t)NN * 256];
__device__ float g_cell1[(size_t)NN * 256];
__device__ float g_sum[(size_t)5 * NSZ];
__device__ float g_nrm[(size_t)5 * NSZ];
__device__ __nv_bfloat16 g_wbk[(size_t)28 * 7 * 8192];  // 7 panels: hi[64][64]+lo[64][64]
__device__ float g_wmix[14 * 8];
__device__ float g_stats[384];
__device__ float g_part[(size_t)MT64 * 3 * 384];
__device__ float g_invdeg[NN];
__device__ float g_invsqrt[NN];
__device__ float g_ew[EE];
__device__ int g_deg[NN];
__device__ int g_cursor[NN];
__device__ int g_rowptr[NN + 1];
__device__ int g_eid[EE];
__device__ int g_srcs[EE];
__device__ int g_bsum[512];

// ---------------- CSR ----------------
__global__ void k_zero2(int* a, int* b) {
    int i = blockIdx.x * blockDim.x + threadIdx.x;
    if (i < NN) { a[i] = 0; b[i] = 0; }
}
__global__ void k_deg(const int* __restrict__ dst, int* __restrict__ deg) {
    int e = blockIdx.x * blockDim.x + threadIdx.x;
    if (e < EE) atomicAdd(&deg[dst[e]], 1);
}
__global__ void k_degfin(const int* __restrict__ deg, float* __restrict__ invdeg,
                         float* __restrict__ invsqrt) {
    int i = blockIdx.x * blockDim.x + threadIdx.x;
    if (i < NN) {
        float d = (float)max(deg[i], 1);
        invdeg[i] = 1.0f / d;
        invsqrt[i] = rsqrtf(d);
    }
}
__global__ void k_scan1(const int* __restrict__ deg, int* __restrict__ rowptr, int* __restrict__ bsum) {
    __shared__ int s[128];
    int b = blockIdx.x, t = threadIdx.x;
    int i = b * 128 + t;
    int v = (i < NN) ? deg[i] : 0;
    s[t] = v;
    __syncthreads();
    for (int off = 1; off < 128; off <<= 1) {
        int u = (t >= off) ? s[t - off] : 0;
        __syncthreads();
        s[t] += u;
        __syncthreads();
    }
    if (i < NN) rowptr[i] = s[t] - v;
    if (t == 127) bsum[b] = s[127];
}
__global__ void k_scan2(int* __restrict__ bsum) {
    __shared__ int s[512];
    int t = threadIdx.x;
    int v = (t < SCAN_B) ? bsum[t] : 0;
    s[t] = v;
    __syncthreads();
    for (int off = 1; off < 512; off <<= 1) {
        int u = (t >= off) ? s[t - off] : 0;
        __syncthreads();
        s[t] += u;
        __syncthreads();
    }
    if (t < SCAN_B) bsum[t] = s[t] - v;
}
__global__ void k_scan3(int* __restrict__ rowptr, const int* __restrict__ bsum) {
    int i = blockIdx.x * blockDim.x + threadIdx.x;
    if (i < NN) rowptr[i] += bsum[i >> 7];
    if (i == 0) rowptr[NN] = EE;
}
__global__ void k_scatter(const int* __restrict__ dst, const int* __restrict__ rowptr,
                          int* __restrict__ cursor, int* __restrict__ eid) {
    int e = blockIdx.x * blockDim.x + threadIdx.x;
    if (e < EE) {
        int d = dst[e];
        int pos = rowptr[d] + atomicAdd(&cursor[d], 1);
        eid[pos] = e;
    }
}
__global__ void k_sortfill(const int* __restrict__ rowptr, int* __restrict__ eid,
                           const int* __restrict__ src, const float* __restrict__ invsqrt,
                           int* __restrict__ srcs, float* __restrict__ ew) {
    int n = blockIdx.x * blockDim.x + threadIdx.x;
    if (n >= NN) return;
    int r0 = rowptr[n], r1 = rowptr[n + 1];
    for (int i = r0 + 1; i < r1; i++) {
        int key = eid[i];
        int j = i - 1;
        while (j >= r0 && eid[j] > key) { eid[j + 1] = eid[j]; j--; }
        eid[j + 1] = key;
    }
    float isd = invsqrt[n];
    for (int p = r0; p < r1; p++) {
        int e = eid[p];
        int s = src[e];
        srcs[p] = s;
        ew[p] = invsqrt[s] * isd;
    }
}
__global__ void k_softmax(const float* __restrict__ alphas, float* __restrict__ wmix) {
    int r = threadIdx.x;
    if (r >= 14) return;
    float m = -1e30f;
    for (int o = 0; o < 8; o++) m = fmaxf(m, alphas[r * 8 + o]);
    float e[8], s = 0.f;
    for (int o = 0; o < 8; o++) { e[o] = expf(alphas[r * 8 + o] - m); s += e[o]; }
    float inv = 1.0f / s;
    for (int o = 0; o < 8; o++) wmix[r * 8 + o] = e[o] * inv;
}

// 7 bf16-split B panels/slot. A sources: p0:h p1:hs p2:mean p3:norm p4:hs p5:h p6:gmix
__global__ void k_bake(const float* __restrict__ wmix,
                       const float* __restrict__ Wgcn, const float* __restrict__ Wss,
                       const float* __restrict__ Wsn, const float* __restrict__ Wgin,
                       const float* __restrict__ Wgc1, const float* __restrict__ Wgc2,
                       const float* __restrict__ Wmlp, const float* __restrict__ Wgcnii,
                       __nv_bfloat16* __restrict__ wbk) {
    int s = blockIdx.x;
    int ej = s % 14;
    const float* wv = wmix + ej * 8;
    size_t o = (size_t)s * 4096;
    __nv_bfloat16* ob = wbk + (size_t)s * 7 * 8192;
    float w1 = wv[1], w2 = wv[2], w3 = wv[3], w4 = wv[4], w5 = wv[5], w6 = wv[6], w7 = wv[7];
    for (int idx = threadIdx.x; idx < 4096; idx += blockDim.x) {
        int k = idx >> 6, n = idx & 63;
        for (int p = 0; p < 7; p++) {
            float v;
            if (p == 0) v = w3 * Wss[o + idx] + w5 * (Wgc1[o + idx] - Wgc2[o + idx]) + ((k == n) ? w1 : 0.f);
            else if (p == 1) v = w5 * Wgc2[o + idx];
            else if (p == 2) v = w3 * Wsn[o + idx];
            else if (p == 3) v = w2 * Wgcn[o + idx];
            else if (p == 4) v = w4 * Wgin[o + idx];
            else if (p == 5) v = w6 * Wmlp[o + idx];
            else v = w7 * Wgcnii[o + idx];
            unsigned short hb, lb;
            bsplit(v, hb, lb);
            ob[p * 8192 + idx] = *(__nv_bfloat16*)&hb;
            ob[p * 8192 + 4096 + idx] = *(__nv_bfloat16*)&lb;
        }
    }
}

// ---------------- fp32 tiled GEMM with fused BN column partials ----------------
__global__ __launch_bounds__(256) void k_gemm(const float* __restrict__ A, int lda,
                                              const float* __restrict__ B, int ldb,
                                              float* __restrict__ C, int K,
                                              float* __restrict__ part) {
    __shared__ float As[TS];
    __shared__ float Bs[TS];
    const int tid = threadIdx.x;
    const int m0 = blockIdx.x * 64;
    const int n0b = blockIdx.y * 64;
    const int tx = tid & 15, ty = tid >> 4;
    const int n0 = tx * 4, mm0 = ty * 4;
    float acc[16];
#pragma unroll
    for (int i = 0; i < 16; i++) acc[i] = 0.f;
    for (int kt = 0; kt < K; kt += 64) {
        __syncthreads();
#pragma unroll
        for (int i = 0; i < 16; i++) {
            int idx = tid + i * 256;
            int m = idx >> 6, k = idx & 63;
            int gm = m0 + m;
            As[k * 68 + m] = (gm < NN) ? A[(size_t)gm * lda + kt + k] : 0.f;
            Bs[(idx >> 6) * 68 + (idx & 63)] = B[(size_t)(kt + (idx >> 6)) * ldb + n0b + (idx & 63)];
        }
        __syncthreads();
#pragma unroll 16
        for (int k = 0; k < 64; k++) {
            float4 a4 = *(const float4*)&As[k * 68 + mm0];
            float4 b4 = *(const float4*)&Bs[k * 68 + n0];
            acc[0] += a4.x * b4.x; acc[1] += a4.x * b4.y; acc[2] += a4.x * b4.z; acc[3] += a4.x * b4.w;
            acc[4] += a4.y * b4.x; acc[5] += a4.y * b4.y; acc[6] += a4.y * b4.z; acc[7] += a4.y * b4.w;
            acc[8] += a4.z * b4.x; acc[9] += a4.z * b4.y; acc[10] += a4.z * b4.z; acc[11] += a4.z * b4.w;
            acc[12] += a4.w * b4.x; acc[13] += a4.w * b4.y; acc[14] += a4.w * b4.z; acc[15] += a4.w * b4.w;
        }
    }
#pragma unroll
    for (int r = 0; r < 4; r++) {
        int gm = m0 + mm0 + r;
        if (gm < NN)
            *(float4*)&C[(size_t)gm * ldb + n0b + n0] =
                make_float4(acc[r * 4], acc[r * 4 + 1], acc[r * 4 + 2], acc[r * 4 + 3]);
    }
    __syncthreads();
#pragma unroll
    for (int c = 0; c < 4; c++) {
        float s = 0.f, q = 0.f;
#pragma unroll
        for (int r = 0; r < 4; r++) {
            if (m0 + mm0 + r < NN) { float v = acc[r * 4 + c]; s += v; q += v * v; }
        }
        As[ty * 64 + n0 + c] = s;
        Bs[ty * 64 + n0 + c] = q;
    }
    __syncthreads();
    if (ty == 0) {
        int blkid = blockIdx.x * gridDim.y + blockIdx.y;
#pragma unroll
        for (int c = 0; c < 4; c++) {
            float s = 0.f, q = 0.f;
#pragma unroll
            for (int t = 0; t < 16; t++) { s += As[t * 64 + n0 + c]; q += Bs[t * 64 + n0 + c]; }
            part[(size_t)blkid * 384 + n0b + n0 + c] = s;
            part[(size_t)blkid * 384 + 192 + n0b + n0 + c] = q;
        }
    }
}

__global__ void k_colfin(const float* __restrict__ part, int ny, float* __restrict__ stats) {
    int c = blockIdx.x, t = threadIdx.x;
    int by = c >> 6;
    float s = 0.f, q = 0.f;
    for (int bx = t; bx < MT64; bx += 256) {
        size_t blk = (size_t)(bx * ny + by) * 384;
        s += part[blk + c];
        q += part[blk + 192 + c];
    }
    __shared__ float rs[256], rq[256];
    rs[t] = s; rq[t] = q;
    __syncthreads();
    for (int o = 128; o > 0; o >>= 1) {
        if (t < o) { rs[t] += rs[t + o]; rq[t] += rq[t + o]; }
        __syncthreads();
    }
    if (t == 0) {
        float m = rs[0] / (float)NN;
        float v = rq[0] / (float)NN - m * m;
        stats[c] = m;
        stats[192 + c] = rsqrtf(v + 1e-5f);
    }
}
__global__ void k_bnapply(float* __restrict__ A, int ncols, const float* __restrict__ stats, int dorelu) {
    size_t idx = (size_t)blockIdx.x * blockDim.x + threadIdx.x;
    if (idx >= (size_t)NN * ncols) return;
    int c = (int)(idx % ncols);
    float v = (A[idx] - stats[c]) * stats[192 + c];
    if (dorelu) v = fmaxf(v, 0.f);
    A[idx] = v;
}
__global__ void k_agg(const float* __restrict__ h, int ldh, const int* __restrict__ rowptr,
                      const int* __restrict__ srcs, const float* __restrict__ ew,
                      float* __restrict__ osum, float* __restrict__ onrm) {
    int warp = (blockIdx.x * blockDim.x + threadIdx.x) >> 5;
    if (warp >= NN) return;
    int lane = threadIdx.x & 31;
    int r0 = rowptr[warp], r1 = rowptr[warp + 1];
    float2 s = make_float2(0.f, 0.f), nrm = make_float2(0.f, 0.f);
    for (int p = r0; p < r1; p++) {
        int si = srcs[p];
        float w = ew[p];
        float2 v = *(const float2*)&h[(size_t)si * ldh + lane * 2];
        s.x += v.x; s.y += v.y;
        nrm.x += w * v.x; nrm.y += w * v.y;
    }
    *(float2*)&osum[(size_t)warp * 64 + lane * 2] = s;
    *(float2*)&onrm[(size_t)warp * 64 + lane * 2] = nrm;
}
__global__ void k_agg2(const float* __restrict__ h0, int l0, const float* __restrict__ h1, int l1,
                       const int* __restrict__ rowptr, const int* __restrict__ srcs,
                       const float* __restrict__ ew,
                       float* __restrict__ sums, float* __restrict__ nrms) {
    int warp = (blockIdx.x * blockDim.x + threadIdx.x) >> 5;
    if (warp >= NN) return;
    int lane = threadIdx.x & 31;
    int r0 = rowptr[warp], r1 = rowptr[warp + 1];
    float2 s0 = make_float2(0.f, 0.f), n0 = make_float2(0.f, 0.f);
    float2 s1 = make_float2(0.f, 0.f), n1 = make_float2(0.f, 0.f);
    for (int p = r0; p < r1; p++) {
        int si = srcs[p];
        float w = ew[p];
        float2 v0 = *(const float2*)&h0[(size_t)si * l0 + lane * 2];
        float2 v1 = *(const float2*)&h1[(size_t)si * l1 + lane * 2];
        s0.x += v0.x; s0.y += v0.y; n0.x += w * v0.x; n0.y += w * v0.y;
        s1.x += v1.x; s1.y += v1.y; n1.x += w * v1.x; n1.y += w * v1.y;
    }
    size_t o = (size_t)warp * 64 + lane * 2;
    *(float2*)&sums[o] = s0;
    *(float2*)&nrms[o] = n0;
    *(float2*)&sums[NSZ + o] = s1;
    *(float2*)&nrms[NSZ + o] = n1;
}

// ---------------- persistent raw-mma bf16-split step kernel: 7 panels, 5 A tiles ----------------
__global__ __launch_bounds__(128, 2) void k_step(
    const float* __restrict__ h0p, const float* __restrict__ h1p, const float* __restrict__ h2p,
    const float* __restrict__ h3p, const float* __restrict__ h4p,
    int l0, int l1, int l2, int l3, int l4,
    const float* __restrict__ sums, const float* __restrict__ nrms,
    const float* __restrict__ x0, const float* __restrict__ invdeg,
    const __nv_bfloat16* __restrict__ wbase, int nst, float* __restrict__ outp) {
    extern __shared__ char smc[];
    const u32 sb = s2u(smc);
    const int tid = threadIdx.x, wid = tid >> 5, lane = tid & 31;
    const int wrow = wid * 16;
    const int fg = lane >> 2, tig = lane & 3;
    const int pa[7] = {AH, AHS, AM, AN, AHS, AH, AG};
    const int prelu[7] = {0, 0, 0, 1, 1, 1, 1};

    for (int m0 = blockIdx.x * 64; m0 < NN; m0 += gridDim.x * 64) {
        float outv[32];
#pragma unroll
        for (int i = 0; i < 32; i++) outv[i] = 0.f;
        uint4 pf[8];
        {
            const uint4* s = (const uint4*)wbase;
#pragma unroll
            for (int i = 0; i < 8; i++) pf[i] = s[tid + i * 128];
        }

        for (int j = 0; j < nst; j++) {
            const float* h = (j == 0) ? h0p : (j == 1) ? h1p : (j == 2) ? h2p : (j == 3) ? h3p : h4p;
            int ldh = (j == 0) ? l0 : (j == 1) ? l1 : (j == 2) ? l2 : (j == 3) ? l3 : l4;
            const float* ssum = sums + (size_t)j * NSZ;
            const float* snrm = nrms + (size_t)j * NSZ;
            const __nv_bfloat16* wslot = wbase + (size_t)j * 7 * 8192;

            __syncthreads();  // prev slot done reading A tiles
#pragma unroll
            for (int i = 0; i < 8; i++) {
                int idx = tid + i * 128;
                int row = idx >> 4, cg = (idx & 15) * 4;
                int gm = m0 + row;
                float4 z = make_float4(0.f, 0.f, 0.f, 0.f);
                float4 hv = z, sv = z, nv = z, xv = z;
                float idg = 0.f;
                if (gm < NN) {
                    hv = *(const float4*)(h + (size_t)gm * ldh + cg);
                    sv = *(const float4*)(ssum + (size_t)gm * 64 + cg);
                    nv = *(const float4*)(snrm + (size_t)gm * 64 + cg);
                    xv = *(const float4*)(x0 + (size_t)gm * 64 + cg);
                    idg = invdeg[gm];
                }
                float4 hs = make_float4(hv.x + sv.x, hv.y + sv.y, hv.z + sv.z, hv.w + sv.w);
                float4 mv = make_float4(sv.x * idg, sv.y * idg, sv.z * idg, sv.w * idg);
                float4 gv = make_float4(0.9f * nv.x + 0.1f * xv.x, 0.9f * nv.y + 0.1f * xv.y,
                                        0.9f * nv.z + 0.1f * xv.z, 0.9f * nv.w + 0.1f * xv.w);
                int off = row * 144 + cg * 2;
                store_split4(smc + AH + off, smc + AH + 9216 + off, hv);
                store_split4(smc + AHS + off, smc + AHS + 9216 + off, hs);
                store_split4(smc + AM + off, smc + AM + 9216 + off, mv);
                store_split4(smc + AN + off, smc + AN + 9216 + off, nv);
                store_split4(smc + AG + off, smc + AG + 9216 + off, gv);
            }

            for (int p = 0; p < 7; p++) {
                __syncthreads();  // B free (prev panel done); A ready at p==0
#pragma unroll
                for (int i = 0; i < 8; i++) {
                    int u = tid + i * 128;
                    int r = u >> 3, c = u & 7;
                    int dst = BOF + ((r < 64) ? (r * 144 + c * 16) : (9216 + (r - 64) * 144 + c * 16));
                    *(uint4*)(smc + dst) = pf[i];
                }
                __syncthreads();
                if (p < 6 || j + 1 < nst) {
                    const uint4* s = (const uint4*)(wslot + (size_t)(p + 1) * 8192);
#pragma unroll
                    for (int i = 0; i < 8; i++) pf[i] = s[tid + i * 128];
                }
                float tc[32];
                float* dst = prelu[p] ? tc : outv;
                if (prelu[p]) {
#pragma unroll
                    for (int i = 0; i < 32; i++) tc[i] = 0.f;
                }
                const u32 At = sb + pa[p];
#pragma unroll
                for (int q = 0; q < 4; q++) {
                    u32 aAddr = At + (u32)((wrow + (lane & 7) + ((lane >> 3) & 1) * 8) * 144 + q * 32 + (lane >> 4) * 16);
                    u32 a0, a1, a2, a3, e0, e1, e2, e3;
                    ldsm4(a0, a1, a2, a3, aAddr);
                    ldsm4(e0, e1, e2, e3, aAddr + 9216);
                    u32 bRow = sb + BOF + (u32)((q * 16 + (lane & 15)) * 144);
#pragma unroll
                    for (int nb = 0; nb < 8; nb++) {
                        u32 b0, b1, c0, c1;
                        ldsm2t(b0, b1, bRow + nb * 16);
                        ldsm2t(c0, c1, bRow + nb * 16 + 9216);
                        mma16816(dst + nb * 4, a0, a1, a2, a3, b0, b1);
                        mma16816(dst + nb * 4, e0, e1, e2, e3, b0, b1);
                        mma16816(dst + nb * 4, a0, a1, a2, a3, c0, c1);
                    }
                }
                if (prelu[p]) {
#pragma unroll
                    for (int i = 0; i < 32; i++) outv[i] += fmaxf(tc[i], 0.f);
                }
            }
        }
        // fragment-layout direct store: thread owns rows (wrow+fg, wrow+fg+8), cols nb*8+tig*2
        int r0g = m0 + wrow + fg, r1g = r0g + 8;
#pragma unroll
        for (int nb = 0; nb < 8; nb++) {
            int c = nb * 8 + tig * 2;
            if (r0g < NN)
                *(float2*)(outp + (size_t)r0g * 256 + c) = make_float2(outv[nb * 4 + 0], outv[nb * 4 + 1]);
            if (r1g < NN)
                *(float2*)(outp + (size_t)r1g * 256 + c) = make_float2(outv[nb * 4 + 2], outv[nb * 4 + 3]);
        }
    }
}

__global__ void k_cls(const float* __restrict__ s1, const float* __restrict__ W,
                      const float* __restrict__ b, float* __restrict__ out) {
    int n = blockIdx.x;
    __shared__ float row[256];
    __shared__ float red[64];
    int tid = threadIdx.x;
    float ls = 0.f;
#pragma unroll
    for (int i = 0; i < 4; i++) {
        float v = s1[(size_t)n * 256 + tid + i * 64];
        row[tid + i * 64] = v;
        ls += v;
    }
    red[tid] = ls;
    __syncthreads();
    for (int off = 32; off > 0; off >>= 1) {
        if (tid < off) red[tid] += red[tid + off];
        __syncthreads();
    }
    float pooled = red[0] * (1.0f / 256.0f);
    if (tid < 40) {
        float acc = b[tid] + pooled * W[tid];
#pragma unroll 8
        for (int k = 0; k < 256; k++) acc += row[k] * W[(1 + k) * 40 + tid];
        out[(size_t)n * 40 + tid] = acc;
    }
}

static void bnrun(float* buf, int ncols, int ny, int dorelu, float* part, float* stats) {
    k_colfin<<<ncols, 256>>>(part, ny, stats);
    size_t total = (size_t)NN * ncols;
    k_bnapply<<<(int)((total + 255) / 256), 256>>>(buf, ncols, stats, dorelu);
}

extern "C" void kernel_launch(void* const* d_in, const int* in_sizes, int n_in,
                              void* d_out, int out_size) {
    const float* x = (const float*)d_in[0];
    const int* ei = (const int*)d_in[1];
    const float* alphas = (const float*)d_in[2];
    const float* stemW = (const float*)d_in[3];
    const float* preW = (const float*)d_in[4];
    const float* p0W0 = (const float*)d_in[5];
    const float* p1W0 = (const float*)d_in[6];
    const float* p0W1 = (const float*)d_in[7];
    const float* p1W1 = (const float*)d_in[8];
    const float* Wgcn = (const float*)d_in[9];
    const float* Wss = (const float*)d_in[10];
    const float* Wsn = (const float*)d_in[11];
    const float* Wgin = (const float*)d_in[12];
    const float* Wgc1 = (const float*)d_in[13];
    const float* Wgc2 = (const float*)d_in[14];
    const float* Wmlp = (const float*)d_in[15];
    const float* Wgcnii = (const float*)d_in[16];
    const float* clsW = (const float*)d_in[17];
    const float* clsb = (const float*)d_in[18];
    float* out = (float*)d_out;
    const int* srcI = ei;
    const int* dstI = ei + EE;

    float *stem, *x0p, *ap, *bp, *c0, *c1, *sums, *nrms, *wmix, *stats, *part;
    float *invdeg, *invsqrt, *ew;
    __nv_bfloat16* wbk;
    int *deg, *cursor, *rowptr, *eid, *srcs, *bsum;
    cudaGetSymbolAddress((void**)&stem, g_stem);
    cudaGetSymbolAddress((void**)&x0p, g_x0);
    cudaGetSymbolAddress((void**)&ap, g_a);
    cudaGetSymbolAddress((void**)&bp, g_b);
    cudaGetSymbolAddress((void**)&c0, g_cell0);
    cudaGetSymbolAddress((void**)&c1, g_cell1);
    cudaGetSymbolAddress((void**)&sums, g_sum);
    cudaGetSymbolAddress((void**)&nrms, g_nrm);
    cudaGetSymbolAddress((void**)&wbk, g_wbk);
    cudaGetSymbolAddress((void**)&wmix, g_wmix);
    cudaGetSymbolAddress((void**)&stats, g_stats);
    cudaGetSymbolAddress((void**)&part, g_part);
    cudaGetSymbolAddress((void**)&invdeg, g_invdeg);
    cudaGetSymbolAddress((void**)&invsqrt, g_invsqrt);
    cudaGetSymbolAddress((void**)&ew, g_ew);
    cudaGetSymbolAddress((void**)&deg, g_deg);
    cudaGetSymbolAddress((void**)&cursor, g_cursor);
    cudaGetSymbolAddress((void**)&rowptr, g_rowptr);
    cudaGetSymbolAddress((void**)&eid, g_eid);
    cudaGetSymbolAddress((void**)&srcs, g_srcs);
    cudaGetSymbolAddress((void**)&bsum, g_bsum);

    cudaFuncSetAttribute(k_step, cudaFuncAttributeMaxDynamicSharedMemorySize, STEP_SMEM);

    k_zero2<<<(NN + 255) / 256, 256>>>(deg, cursor);
    k_deg<<<(EE + 255) / 256, 256>>>(dstI, deg);
    k_degfin<<<(NN + 255) / 256, 256>>>(deg, invdeg, invsqrt);
    k_scan1<<<SCAN_B, 128>>>(deg, rowptr, bsum);
    k_scan2<<<1, 512>>>(bsum);
    k_scan3<<<(NN + 255) / 256, 256>>>(rowptr, bsum);
    k_scatter<<<(EE + 255) / 256, 256>>>(dstI, rowptr, cursor, eid);
    k_sortfill<<<(NN + 127) / 128, 128>>>(rowptr, eid, srcI, invsqrt, srcs, ew);

    k_softmax<<<1, 16>>>(alphas, wmix);
    k_bake<<<28, 256>>>(wmix, Wgcn, Wss, Wsn, Wgin, Wgc1, Wgc2, Wmlp, Wgcnii, wbk);

    k_gemm<<<dim3(MT64, 3), 256>>>(x, 128, stemW, 192, stem, 128, part);
    bnrun(stem, 192, 3, 0, part, stats);
    k_gemm<<<dim3(MT64, 1), 256>>>(x, 128, preW, 64, x0p, 128, part);
    bnrun(x0p, 64, 1, 1, part, stats);

    const int aggBlocks = (NN * 32 + 255) / 256;
    for (int ci = 0; ci < 2; ci++) {
        const float* s0 = stem; int k0 = 192;
        const float* s1 = (ci == 0) ? stem : c0;
        int k1 = (ci == 0) ? 192 : 256;
        const float* pW0 = (ci == 0) ? p0W0 : p0W1;
        const float* pW1 = (ci == 0) ? p1W0 : p1W1;
        float* cell = (ci == 0) ? c0 : c1;

        k_gemm<<<dim3(MT64, 1), 256>>>(s0, k0, pW0, 64, ap, k0, part);
        bnrun(ap, 64, 1, 1, part, stats);
        k_gemm<<<dim3(MT64, 1), 256>>>(s1, k1, pW1, 64, bp, k1, part);
        bnrun(bp, 64, 1, 1, part, stats);

        const float* sp[5] = {ap, bp, cell, cell + 64, cell + 128};
        const int sl[5] = {64, 64, 256, 256, 256};
        k_agg2<<<aggBlocks, 256>>>(sp[0], sl[0], sp[1], sl[1], rowptr, srcs, ew, sums, nrms);

        int ej0 = 0;
        for (int t = 0; t < 4; t++) {
            const __nv_bfloat16* wb = wbk + (size_t)(ci * 14 + ej0) * 7 * 8192;
            k_step<<<PGRID, 128, STEP_SMEM>>>(sp[0], sp[1], sp[2], sp[3], sp[4],
                                              sl[0], sl[1], sl[2], sl[3], sl[4],
                                              sums, nrms, x0p, invdeg, wb, t + 2, cell + t * 64);
            ej0 += t + 2;
            if (t < 3) {
                int ns = t + 2;
                k_agg<<<aggBlocks, 256>>>(sp[ns], sl[ns], rowptr, srcs, ew,
                                          sums + (size_t)ns * NSZ, nrms + (size_t)ns * NSZ);
            }
        }
    }
    k_cls<<<NN, 64>>>(c1, clsW, clsb, out);
}